// round 3
// baseline (speedup 1.0000x reference)
#include <cuda_runtime.h>
#include <stdint.h>

#define NMAX 50000
#define EMAX 800000
#define HID 128
#define FEAT 64

// ---------------- scratch (static device globals; no allocation) ----------------
__device__ float g_xA[(size_t)NMAX * HID];
__device__ float g_xB[(size_t)NMAX * HID];
__device__ float g_agg[(size_t)NMAX * 3 * HID];   // [node][rel][128], pre-scaled by 1/deg
__device__ int   g_counts[NMAX];
__device__ int   g_off[NMAX + 1];
__device__ int   g_cursor[NMAX];
__device__ int   g_csr[EMAX];                      // packed: (src<<2)|etype
__device__ int   g_tcnt[4];
__device__ int   g_tlist[4 * NMAX];
__device__ float g_pooled[HID];
__device__ int   g_bsum[64];
__device__ int   g_bpre[64];

// ---------------- f32x2 packed helpers (Blackwell) ----------------
__device__ __forceinline__ unsigned long long pk2(float lo, float hi) {
    unsigned long long r;
    asm("mov.b64 %0, {%1, %2};" : "=l"(r) : "f"(lo), "f"(hi));
    return r;
}
__device__ __forceinline__ void upk2(unsigned long long v, float& lo, float& hi) {
    asm("mov.b64 {%0, %1}, %2;" : "=f"(lo), "=f"(hi) : "l"(v));
}
__device__ __forceinline__ unsigned long long ffma2(unsigned long long a,
                                                    unsigned long long b,
                                                    unsigned long long c) {
    unsigned long long d;
    asm("fma.rn.f32x2 %0, %1, %2, %3;" : "=l"(d) : "l"(a), "l"(b), "l"(c));
    return d;
}

// ---------------- small setup kernels ----------------
__global__ void k_init(int n) {
    int i = blockIdx.x * blockDim.x + threadIdx.x;
    if (i < n) { g_counts[i] = 0; g_cursor[i] = 0; }
    if (i < HID) g_pooled[i] = 0.f;
    if (i < 4) g_tcnt[i] = 0;
}

__global__ void k_count_deg(const int* __restrict__ ei, int nE) {
    int e = blockIdx.x * blockDim.x + threadIdx.x;
    if (e < nE) atomicAdd(&g_counts[ei[nE + e]], 1);
}

// type bucketing with per-block smem counters (avoids 50K atomics onto 4 addrs)
__global__ void __launch_bounds__(256) k_bucket(const int* __restrict__ nt, int n) {
    __shared__ int cnt[4];
    __shared__ int basei[4];
    __shared__ unsigned cur[4];
    int t = threadIdx.x;
    if (t < 4) { cnt[t] = 0; cur[t] = 0; }
    __syncthreads();
    int i = blockIdx.x * blockDim.x + t;
    int ty = (i < n) ? nt[i] : -1;
    if (ty >= 0) atomicAdd(&cnt[ty], 1);
    __syncthreads();
    if (t < 4) basei[t] = atomicAdd(&g_tcnt[t], cnt[t]);
    __syncthreads();
    if (ty >= 0) {
        int pos = atomicAdd(&cur[ty], 1u);
        g_tlist[ty * NMAX + basei[ty] + pos] = i;
    }
}

// ---------------- 3-phase multi-block exclusive scan of g_counts ----------------
__global__ void __launch_bounds__(256) k_scan1(int n) {
    int b = blockIdx.x, t = threadIdx.x;
    int base = b * 1024 + t * 4;
    int s = 0;
    if (base + 3 < n) {
        int4 c = *(const int4*)&g_counts[base];
        s = c.x + c.y + c.z + c.w;
    } else {
        for (int q = 0; q < 4; ++q) if (base + q < n) s += g_counts[base + q];
    }
#pragma unroll
    for (int o = 16; o; o >>= 1) s += __shfl_xor_sync(0xffffffffu, s, o);
    __shared__ int ws[8];
    if ((t & 31) == 0) ws[t >> 5] = s;
    __syncthreads();
    if (t == 0) {
        int tot = 0;
#pragma unroll
        for (int w = 0; w < 8; ++w) tot += ws[w];
        g_bsum[b] = tot;
    }
}

__global__ void k_scan2(int nb) {
    int lane = threadIdx.x;
    int carry = 0;
    for (int base = 0; base < nb; base += 32) {
        int i = base + lane;
        int v = (i < nb) ? g_bsum[i] : 0;
        int x = v;
#pragma unroll
        for (int d = 1; d < 32; d <<= 1) {
            int u = __shfl_up_sync(0xffffffffu, x, d);
            if (lane >= d) x += u;
        }
        if (i < nb) g_bpre[i] = carry + x - v;
        carry += __shfl_sync(0xffffffffu, x, 31);
    }
}

__global__ void __launch_bounds__(256) k_scan3(int n) {
    __shared__ int wsum[8];
    int b = blockIdx.x, t = threadIdx.x, lane = t & 31, w = t >> 5;
    int base = b * 1024 + t * 4;
    int v0 = 0, v1 = 0, v2 = 0, v3 = 0;
    if (base + 3 < n) {
        int4 c = *(const int4*)&g_counts[base];
        v0 = c.x; v1 = c.y; v2 = c.z; v3 = c.w;
    } else {
        if (base < n) v0 = g_counts[base];
        if (base + 1 < n) v1 = g_counts[base + 1];
        if (base + 2 < n) v2 = g_counts[base + 2];
        if (base + 3 < n) v3 = g_counts[base + 3];
    }
    int s = v0 + v1 + v2 + v3;
    int x = s;
#pragma unroll
    for (int d = 1; d < 32; d <<= 1) {
        int u = __shfl_up_sync(0xffffffffu, x, d);
        if (lane >= d) x += u;
    }
    if (lane == 31) wsum[w] = x;
    __syncthreads();
    if (t == 0) {
        int run = 0;
#pragma unroll
        for (int q = 0; q < 8; ++q) { int tmp = wsum[q]; wsum[q] = run; run += tmp; }
    }
    __syncthreads();
    int pre = g_bpre[b] + wsum[w] + (x - s);
    int r = pre;
    r += v0; if (base < n)     g_off[base + 1] = r;
    r += v1; if (base + 1 < n) g_off[base + 2] = r;
    r += v2; if (base + 2 < n) g_off[base + 3] = r;
    r += v3; if (base + 3 < n) g_off[base + 4] = r;
    if (b == 0 && t == 0) g_off[0] = 0;
}

__global__ void k_scatter(const int* __restrict__ ei, const int* __restrict__ et, int nE) {
    int e = blockIdx.x * blockDim.x + threadIdx.x;
    if (e >= nE) return;
    int d = ei[nE + e];
    int pos = g_off[d] + atomicAdd(&g_cursor[d], 1);
    g_csr[pos] = (ei[e] << 2) | (et[e] & 3);
}

// ---------------- typed encoder: 64 nodes of one type per block, f32x2 packed ----------------
__global__ void __launch_bounds__(128) k_encoder(
    const int* __restrict__ z, const float* __restrict__ z_embed,
    const float* __restrict__ w1, const float* __restrict__ b1,
    const float* __restrict__ w2, const float* __restrict__ b2, int n)
{
    int t = blockIdx.y;
    int cntT = g_tcnt[t];
    int base = blockIdx.x * 64;
    if (base >= cntT) return;
    int cnt = min(64, cntT - base);

    __shared__ int   nds[64];
    __shared__ int   zz[64];
    __shared__ float raw_s[64][68];   // [d][node]
    __shared__ float h_s[HID][68];    // [k][node]

    int tid = threadIdx.x;
    if (tid < 64) {
        int idx = (tid < cnt) ? tid : 0;
        int node = g_tlist[t * NMAX + base + idx];
        nds[tid] = node;
        zz[tid] = z[node] * FEAT;
    }
    __syncthreads();

#pragma unroll
    for (int it = 0; it < 32; ++it) {
        int e = tid + it * 128;
        int nn = e >> 6, d = e & 63;
        raw_s[d][nn] = z_embed[zz[nn] + d];
    }
    __syncthreads();

    int j = tid;
    const float* W1 = w1 + (size_t)t * FEAT * HID;
    unsigned long long acc[32];
    {
        float bb = b1[t * HID + j];
        unsigned long long bb2 = pk2(bb, bb);
#pragma unroll
        for (int m = 0; m < 32; ++m) acc[m] = bb2;
    }

    for (int d = 0; d < FEAT; ++d) {
        float w = __ldg(&W1[(size_t)d * HID + j]);
        unsigned long long w2 = pk2(w, w);
        const ulonglong2* rp = (const ulonglong2*)&raw_s[d][0];
#pragma unroll
        for (int q = 0; q < 16; ++q) {
            ulonglong2 r = rp[q];
            acc[2 * q]     = ffma2(r.x, w2, acc[2 * q]);
            acc[2 * q + 1] = ffma2(r.y, w2, acc[2 * q + 1]);
        }
    }
    // relu + transpose into h_s
#pragma unroll
    for (int m = 0; m < 32; ++m) {
        float lo, hi;
        upk2(acc[m], lo, hi);
        float2 v;
        v.x = fmaxf(lo, 0.f);
        v.y = fmaxf(hi, 0.f);
        *(float2*)&h_s[j][2 * m] = v;
    }
    __syncthreads();

    const float* W2 = w2 + (size_t)t * HID * HID;
    {
        float bb = b2[t * HID + j];
        unsigned long long bb2 = pk2(bb, bb);
#pragma unroll
        for (int m = 0; m < 32; ++m) acc[m] = bb2;
    }

    for (int k = 0; k < HID; ++k) {
        float w = __ldg(&W2[(size_t)k * HID + j]);
        unsigned long long w2 = pk2(w, w);
        const ulonglong2* hp = (const ulonglong2*)&h_s[k][0];
#pragma unroll
        for (int q = 0; q < 16; ++q) {
            ulonglong2 r = hp[q];
            acc[2 * q]     = ffma2(r.x, w2, acc[2 * q]);
            acc[2 * q + 1] = ffma2(r.y, w2, acc[2 * q + 1]);
        }
    }
#pragma unroll
    for (int m = 0; m < 32; ++m) {
        float lo, hi;
        upk2(acc[m], lo, hi);
        if (2 * m < cnt)     g_xA[(size_t)nds[2 * m] * HID + j] = lo;
        if (2 * m + 1 < cnt) g_xA[(size_t)nds[2 * m + 1] * HID + j] = hi;
    }
}

// ---------------- per-node relational aggregation (warp per node, MLP=4) ----------------
__device__ __forceinline__ void acc4(float4& a, const float4& v) {
    a.x += v.x; a.y += v.y; a.z += v.z; a.w += v.w;
}

__global__ void k_aggregate(int sel, int n) {
    int gw = (blockIdx.x * blockDim.x + threadIdx.x) >> 5;
    if (gw >= n) return;
    const float* __restrict__ x = sel ? g_xB : g_xA;
    int lane = threadIdx.x & 31;
    int s = g_off[gw], e = g_off[gw + 1];
    int deg = e - s;
    float inv = 1.f / (float)(deg >= 1 ? deg : 1);
    float4 a0 = make_float4(0, 0, 0, 0), a1 = a0, a2 = a0;
    int lo4 = lane * 4;
    int i = s;
    for (; i + 4 <= e; i += 4) {
        int p0 = g_csr[i], p1 = g_csr[i + 1], p2 = g_csr[i + 2], p3 = g_csr[i + 3];
        float4 v0 = *(const float4*)(x + (size_t)(p0 >> 2) * HID + lo4);
        float4 v1 = *(const float4*)(x + (size_t)(p1 >> 2) * HID + lo4);
        float4 v2 = *(const float4*)(x + (size_t)(p2 >> 2) * HID + lo4);
        float4 v3 = *(const float4*)(x + (size_t)(p3 >> 2) * HID + lo4);
        int e0 = p0 & 3;
        if (e0 == 0) acc4(a0, v0); else if (e0 == 1) acc4(a1, v0); else acc4(a2, v0);
        int e1 = p1 & 3;
        if (e1 == 0) acc4(a0, v1); else if (e1 == 1) acc4(a1, v1); else acc4(a2, v1);
        int e2 = p2 & 3;
        if (e2 == 0) acc4(a0, v2); else if (e2 == 1) acc4(a1, v2); else acc4(a2, v2);
        int e3 = p3 & 3;
        if (e3 == 0) acc4(a0, v3); else if (e3 == 1) acc4(a1, v3); else acc4(a2, v3);
    }
    for (; i < e; ++i) {
        int p = g_csr[i];
        float4 v = *(const float4*)(x + (size_t)(p >> 2) * HID + lo4);
        int et = p & 3;
        if (et == 0) acc4(a0, v); else if (et == 1) acc4(a1, v); else acc4(a2, v);
    }
    float* o = g_agg + (size_t)gw * 384 + lo4;
    a0.x *= inv; a0.y *= inv; a0.z *= inv; a0.w *= inv;
    a1.x *= inv; a1.y *= inv; a1.z *= inv; a1.w *= inv;
    a2.x *= inv; a2.y *= inv; a2.z *= inv; a2.w *= inv;
    *(float4*)(o)       = a0;
    *(float4*)(o + 128) = a1;
    *(float4*)(o + 256) = a2;
}

// ---------------- fused [N,512]@[512,128] GEMM + bias + LayerNorm ----------------
__global__ void __launch_bounds__(256) k_gemm_ln(
    int layer,
    const float* __restrict__ lin_w_all, const float* __restrict__ lin_b_all,
    const float* __restrict__ rel_w_all,
    const float* __restrict__ ln_g_all, const float* __restrict__ ln_b_all, int n)
{
    const float* xin  = layer ? g_xB : g_xA;
    float* xout       = layer ? g_xA : g_xB;
    const float* linW = lin_w_all + (size_t)layer * HID * HID;
    const float* relW = rel_w_all + (size_t)layer * 3 * HID * HID;
    const float* lnG  = ln_g_all + layer * HID;
    const float* lnB  = ln_b_all + layer * HID;

    __shared__ float As[32][68];
    __shared__ float Ws[32][HID];
    __shared__ float Ys[64][HID + 4];

    int tid = threadIdx.x;
    int j = tid & 127;
    int g = tid >> 7;
    int base = blockIdx.x * 64;

    float linb = lin_b_all[layer * HID + j];
    unsigned long long acc[16];
    unsigned long long initv = pk2(linb, linb);
#pragma unroll
    for (int m = 0; m < 16; ++m) acc[m] = initv;

    for (int s = 0; s < 4; ++s) {
        const float* wseg = (s == 0) ? linW : relW + (size_t)(s - 1) * HID * HID;
        const float* aseg = (s == 0) ? xin : g_agg + (s - 1) * HID;
        int astride = (s == 0) ? HID : 3 * HID;
        for (int kb = 0; kb < HID; kb += 32) {
            __syncthreads();
#pragma unroll
            for (int it = 0; it < 8; ++it) {
                int e = tid + it * 256;
                int nl = e >> 5, k = e & 31;
                int node = base + nl;
                As[k][nl] = (node < n) ? aseg[(size_t)node * astride + kb + k] : 0.f;
            }
#pragma unroll
            for (int it = 0; it < 16; ++it) {
                int e = tid + it * 256;
                int k = e >> 7, jj = e & 127;
                Ws[k][jj] = __ldg(&wseg[(size_t)(kb + k) * HID + jj]);
            }
            __syncthreads();
#pragma unroll
            for (int k = 0; k < 32; ++k) {
                float w = Ws[k][j];
                unsigned long long w2 = pk2(w, w);
                const ulonglong2* ap = (const ulonglong2*)&As[k][g * 32];
#pragma unroll
                for (int q = 0; q < 8; ++q) {
                    ulonglong2 a = ap[q];
                    acc[2 * q]     = ffma2(a.x, w2, acc[2 * q]);
                    acc[2 * q + 1] = ffma2(a.y, w2, acc[2 * q + 1]);
                }
            }
        }
    }
    __syncthreads();
#pragma unroll
    for (int m = 0; m < 16; ++m) {
        float lo, hi;
        upk2(acc[m], lo, hi);
        Ys[g * 32 + 2 * m][j]     = lo;
        Ys[g * 32 + 2 * m + 1][j] = hi;
    }
    __syncthreads();

    int lane = tid & 31, wid = tid >> 5;
    float4 g4 = *(const float4*)(lnG + lane * 4);
    float4 b4 = *(const float4*)(lnB + lane * 4);
    for (int nn = wid; nn < 64; nn += 8) {
        int node = base + nn;
        if (node >= n) break;
        float4 y = *(const float4*)&Ys[nn][lane * 4];
        float s1 = y.x + y.y + y.z + y.w;
        float s2 = y.x * y.x + y.y * y.y + y.z * y.z + y.w * y.w;
#pragma unroll
        for (int o = 16; o; o >>= 1) {
            s1 += __shfl_xor_sync(0xffffffffu, s1, o);
            s2 += __shfl_xor_sync(0xffffffffu, s2, o);
        }
        float mu = s1 * (1.f / 128.f);
        float var = s2 * (1.f / 128.f) - mu * mu;
        float rs = rsqrtf(var + 1e-5f);
        float4 o4;
        o4.x = (y.x - mu) * rs * g4.x + b4.x;
        o4.y = (y.y - mu) * rs * g4.y + b4.y;
        o4.z = (y.z - mu) * rs * g4.z + b4.z;
        o4.w = (y.w - mu) * rs * g4.w + b4.w;
        *(float4*)&xout[(size_t)node * HID + lane * 4] = o4;
    }
}

// ---------------- pooling + regression head ----------------
__global__ void k_pool(int n) {
    int j = threadIdx.x & 127;
    int h = threadIdx.x >> 7;
    float s = 0.f;
    for (int node = blockIdx.x * 2 + h; node < n; node += gridDim.x * 2)
        s += g_xA[(size_t)node * HID + j];
    atomicAdd(&g_pooled[j], s);
}

__global__ void k_final(const float* __restrict__ reg_w, const float* __restrict__ reg_b,
                        float* __restrict__ out, int n) {
    int tid = threadIdx.x;
    float v = g_pooled[tid] * (1.f / (float)n) * reg_w[tid];
#pragma unroll
    for (int o = 16; o; o >>= 1) v += __shfl_xor_sync(0xffffffffu, v, o);
    __shared__ float r[4];
    if ((tid & 31) == 0) r[tid >> 5] = v;
    __syncthreads();
    if (tid == 0) out[0] = r[0] + r[1] + r[2] + r[3] + reg_b[0];
}

// ---------------- launch ----------------
extern "C" void kernel_launch(void* const* d_in, const int* in_sizes, int n_in,
                              void* d_out, int out_size) {
    const int*   z          = (const int*)d_in[0];
    const int*   node_type  = (const int*)d_in[1];
    const int*   edge_index = (const int*)d_in[2];
    const int*   edge_type  = (const int*)d_in[3];
    const float* z_embed    = (const float*)d_in[4];
    const float* enc_w1     = (const float*)d_in[5];
    const float* enc_b1     = (const float*)d_in[6];
    const float* enc_w2     = (const float*)d_in[7];
    const float* enc_b2     = (const float*)d_in[8];
    const float* lin_w      = (const float*)d_in[9];
    const float* lin_b      = (const float*)d_in[10];
    const float* rel_w      = (const float*)d_in[11];
    const float* ln_g       = (const float*)d_in[12];
    const float* ln_b       = (const float*)d_in[13];
    const float* reg_w      = (const float*)d_in[14];
    const float* reg_b      = (const float*)d_in[15];
    float* out = (float*)d_out;

    int n = in_sizes[0];
    int E = in_sizes[3];
    int nb = (n + 1023) / 1024;

    k_init<<<(n + 255) / 256, 256>>>(n);
    k_count_deg<<<(E + 255) / 256, 256>>>(edge_index, E);
    k_bucket<<<(n + 255) / 256, 256>>>(node_type, n);
    k_scan1<<<nb, 256>>>(n);
    k_scan2<<<1, 32>>>(nb);
    k_scan3<<<nb, 256>>>(n);
    k_scatter<<<(E + 255) / 256, 256>>>(edge_index, edge_type, E);

    dim3 egrid((n + 63) / 64, 4);
    k_encoder<<<egrid, 128>>>(z, z_embed, enc_w1, enc_b1, enc_w2, enc_b2, n);

    int agrid = (n * 32 + 255) / 256;
    k_aggregate<<<agrid, 256>>>(0, n);
    k_gemm_ln<<<(n + 63) / 64, 256>>>(0, lin_w, lin_b, rel_w, ln_g, ln_b, n);
    k_aggregate<<<agrid, 256>>>(1, n);
    k_gemm_ln<<<(n + 63) / 64, 256>>>(1, lin_w, lin_b, rel_w, ln_g, ln_b, n);

    k_pool<<<128, 256>>>(n);
    k_final<<<1, 128>>>(reg_w, reg_b, out, n);
}

// round 5
// speedup vs baseline: 1.2051x; 1.2051x over previous
#include <cuda_runtime.h>
#include <cuda_bf16.h>
#include <stdint.h>

#define NMAX 50000
#define EMAX 800000
#define HID 128
#define FEAT 64
#define ASTRIDE 36   // u32 words per 64-k row (144B) -> conflict-free fragment LDS

__device__ float g_xA[(size_t)NMAX * HID];
__device__ float g_xB[(size_t)NMAX * HID];
__device__ uint32_t g_xAp[(size_t)NMAX * HID];   // packed bf16 hi|lo<<16
__device__ uint32_t g_xBp[(size_t)NMAX * HID];
__device__ uint32_t g_aggp[(size_t)NMAX * 384];
__device__ uint32_t g_wtpk[2 * 128 * 512];       // [l][j][kglob] packed hi|lo
__device__ int   g_counts[NMAX];
__device__ int   g_off[NMAX + 1];
__device__ int   g_cursor[NMAX];
__device__ int   g_csr[EMAX];
__device__ int   g_tcnt[4];
__device__ int   g_tlist[4 * NMAX];
__device__ float g_pooled[HID];
__device__ int   g_bsum[64];
__device__ int   g_bpre[64];

// ---- f32x2 helpers ----
__device__ __forceinline__ unsigned long long pk2(float lo, float hi) {
    unsigned long long r; asm("mov.b64 %0, {%1, %2};" : "=l"(r) : "f"(lo), "f"(hi)); return r;
}
__device__ __forceinline__ void upk2(unsigned long long v, float& lo, float& hi) {
    asm("mov.b64 {%0, %1}, %2;" : "=f"(lo), "=f"(hi) : "l"(v));
}
__device__ __forceinline__ unsigned long long ffma2(unsigned long long a, unsigned long long b, unsigned long long c) {
    unsigned long long d; asm("fma.rn.f32x2 %0, %1, %2, %3;" : "=l"(d) : "l"(a), "l"(b), "l"(c)); return d;
}
__device__ __forceinline__ uint32_t pkbf(float v) {
    __nv_bfloat16 h = __float2bfloat16(v);
    __nv_bfloat16 l = __float2bfloat16(v - __bfloat162float(h));
    return (uint32_t)__bfloat16_as_ushort(h) | ((uint32_t)__bfloat16_as_ushort(l) << 16);
}

// ---- warp-level bf16 HMMA (plain PTX ISA, no arch-feature gate) ----
__device__ __forceinline__ void mma16816(float* c, const uint32_t* a, const uint32_t* b) {
    asm volatile(
        "mma.sync.aligned.m16n8k16.row.col.f32.bf16.bf16.f32 "
        "{%0,%1,%2,%3}, {%4,%5,%6,%7}, {%8,%9}, {%0,%1,%2,%3};"
        : "+f"(c[0]), "+f"(c[1]), "+f"(c[2]), "+f"(c[3])
        : "r"(a[0]), "r"(a[1]), "r"(a[2]), "r"(a[3]), "r"(b[0]), "r"(b[1]));
}

// ---- setup ----
__global__ void k_init(int n) {
    int i = blockIdx.x * blockDim.x + threadIdx.x;
    if (i < n) { g_counts[i] = 0; g_cursor[i] = 0; }
    if (i < HID) g_pooled[i] = 0.f;
    if (i < 4) g_tcnt[i] = 0;
}
__global__ void k_count_deg(const int* __restrict__ ei, int nE) {
    int e = blockIdx.x * blockDim.x + threadIdx.x;
    if (e < nE) atomicAdd(&g_counts[ei[nE + e]], 1);
}
__global__ void __launch_bounds__(256) k_bucket(const int* __restrict__ nt, int n) {
    __shared__ int cnt[4]; __shared__ int basei[4]; __shared__ unsigned cur[4];
    int t = threadIdx.x;
    if (t < 4) { cnt[t] = 0; cur[t] = 0; }
    __syncthreads();
    int i = blockIdx.x * blockDim.x + t;
    int ty = (i < n) ? nt[i] : -1;
    if (ty >= 0) atomicAdd(&cnt[ty], 1);
    __syncthreads();
    if (t < 4) basei[t] = atomicAdd(&g_tcnt[t], cnt[t]);
    __syncthreads();
    if (ty >= 0) { int pos = atomicAdd(&cur[ty], 1u); g_tlist[ty * NMAX + basei[ty] + pos] = i; }
}
__global__ void k_prep_w(const float* __restrict__ lin_w, const float* __restrict__ rel_w) {
    int idx = blockIdx.x * 256 + threadIdx.x;
    if (idx >= 2 * 128 * 512) return;
    int l = idx >> 16, j = (idx >> 9) & 127, kg = idx & 511;
    float w = (kg < 128) ? lin_w[l * 16384 + kg * 128 + j] : rel_w[l * 49152 + (kg - 128) * 128 + j];
    g_wtpk[idx] = pkbf(w);
}
__global__ void __launch_bounds__(256) k_scan1(int n) {
    int b = blockIdx.x, t = threadIdx.x;
    int base = b * 1024 + t * 4;
    int s = 0;
    if (base + 3 < n) { int4 c = *(const int4*)&g_counts[base]; s = c.x + c.y + c.z + c.w; }
    else for (int q = 0; q < 4; ++q) if (base + q < n) s += g_counts[base + q];
#pragma unroll
    for (int o = 16; o; o >>= 1) s += __shfl_xor_sync(0xffffffffu, s, o);
    __shared__ int ws[8];
    if ((t & 31) == 0) ws[t >> 5] = s;
    __syncthreads();
    if (t == 0) { int tot = 0; for (int w = 0; w < 8; ++w) tot += ws[w]; g_bsum[b] = tot; }
}
__global__ void k_scan2(int nb) {
    int lane = threadIdx.x; int carry = 0;
    for (int base = 0; base < nb; base += 32) {
        int i = base + lane;
        int v = (i < nb) ? g_bsum[i] : 0, x = v;
#pragma unroll
        for (int d = 1; d < 32; d <<= 1) { int u = __shfl_up_sync(0xffffffffu, x, d); if (lane >= d) x += u; }
        if (i < nb) g_bpre[i] = carry + x - v;
        carry += __shfl_sync(0xffffffffu, x, 31);
    }
}
__global__ void __launch_bounds__(256) k_scan3(int n) {
    __shared__ int wsum[8];
    int b = blockIdx.x, t = threadIdx.x, lane = t & 31, w = t >> 5;
    int base = b * 1024 + t * 4;
    int v0 = 0, v1 = 0, v2 = 0, v3 = 0;
    if (base + 3 < n) { int4 c = *(const int4*)&g_counts[base]; v0 = c.x; v1 = c.y; v2 = c.z; v3 = c.w; }
    else { if (base < n) v0 = g_counts[base]; if (base + 1 < n) v1 = g_counts[base + 1];
           if (base + 2 < n) v2 = g_counts[base + 2]; if (base + 3 < n) v3 = g_counts[base + 3]; }
    int s = v0 + v1 + v2 + v3, x = s;
#pragma unroll
    for (int d = 1; d < 32; d <<= 1) { int u = __shfl_up_sync(0xffffffffu, x, d); if (lane >= d) x += u; }
    if (lane == 31) wsum[w] = x;
    __syncthreads();
    if (t == 0) { int run = 0; for (int q = 0; q < 8; ++q) { int tmp = wsum[q]; wsum[q] = run; run += tmp; } }
    __syncthreads();
    int r = g_bpre[b] + wsum[w] + (x - s);
    r += v0; if (base < n)     g_off[base + 1] = r;
    r += v1; if (base + 1 < n) g_off[base + 2] = r;
    r += v2; if (base + 2 < n) g_off[base + 3] = r;
    r += v3; if (base + 3 < n) g_off[base + 4] = r;
    if (b == 0 && t == 0) g_off[0] = 0;
}
__global__ void k_scatter(const int* __restrict__ ei, const int* __restrict__ et, int nE) {
    int e = blockIdx.x * blockDim.x + threadIdx.x;
    if (e >= nE) return;
    int d = ei[nE + e];
    int pos = g_off[d] + atomicAdd(&g_cursor[d], 1);
    g_csr[pos] = (ei[e] << 2) | (et[e] & 3);
}

// ---- typed encoder ----
__global__ void __launch_bounds__(128) k_encoder(
    const int* __restrict__ z, const float* __restrict__ z_embed,
    const float* __restrict__ w1, const float* __restrict__ b1,
    const float* __restrict__ w2, const float* __restrict__ b2, int n)
{
    int t = blockIdx.y;
    int cntT = g_tcnt[t];
    int base = blockIdx.x * 64;
    if (base >= cntT) return;
    int cnt = min(64, cntT - base);
    __shared__ int nds[64]; __shared__ int zz[64];
    __shared__ float raw_s[64][68]; __shared__ float h_s[HID][68];
    int tid = threadIdx.x;
    if (tid < 64) {
        int idx = (tid < cnt) ? tid : 0;
        int node = g_tlist[t * NMAX + base + idx];
        nds[tid] = node; zz[tid] = z[node] * FEAT;
    }
    __syncthreads();
#pragma unroll
    for (int it = 0; it < 32; ++it) {
        int e = tid + it * 128;
        raw_s[e & 63][e >> 6] = z_embed[zz[e >> 6] + (e & 63)];
    }
    __syncthreads();
    int j = tid;
    const float* W1 = w1 + (size_t)t * FEAT * HID;
    unsigned long long acc[32];
    { float bb = b1[t * HID + j]; unsigned long long b2v = pk2(bb, bb);
#pragma unroll
      for (int m = 0; m < 32; ++m) acc[m] = b2v; }
    for (int d = 0; d < FEAT; ++d) {
        float w = __ldg(&W1[(size_t)d * HID + j]);
        unsigned long long w2 = pk2(w, w);
        const ulonglong2* rp = (const ulonglong2*)&raw_s[d][0];
#pragma unroll
        for (int q = 0; q < 16; ++q) { ulonglong2 r = rp[q]; acc[2 * q] = ffma2(r.x, w2, acc[2 * q]); acc[2 * q + 1] = ffma2(r.y, w2, acc[2 * q + 1]); }
    }
#pragma unroll
    for (int m = 0; m < 32; ++m) {
        float lo, hi; upk2(acc[m], lo, hi);
        float2 v; v.x = fmaxf(lo, 0.f); v.y = fmaxf(hi, 0.f);
        *(float2*)&h_s[j][2 * m] = v;
    }
    __syncthreads();
    const float* W2 = w2 + (size_t)t * HID * HID;
    { float bb = b2[t * HID + j]; unsigned long long b2v = pk2(bb, bb);
#pragma unroll
      for (int m = 0; m < 32; ++m) acc[m] = b2v; }
    for (int k = 0; k < HID; ++k) {
        float w = __ldg(&W2[(size_t)k * HID + j]);
        unsigned long long w2 = pk2(w, w);
        const ulonglong2* hp = (const ulonglong2*)&h_s[k][0];
#pragma unroll
        for (int q = 0; q < 16; ++q) { ulonglong2 r = hp[q]; acc[2 * q] = ffma2(r.x, w2, acc[2 * q]); acc[2 * q + 1] = ffma2(r.y, w2, acc[2 * q + 1]); }
    }
#pragma unroll
    for (int m = 0; m < 32; ++m) {
        float lo, hi; upk2(acc[m], lo, hi);
        if (2 * m < cnt)     { size_t o = (size_t)nds[2 * m] * HID + j;     g_xA[o] = lo; g_xAp[o] = pkbf(lo); }
        if (2 * m + 1 < cnt) { size_t o = (size_t)nds[2 * m + 1] * HID + j; g_xA[o] = hi; g_xAp[o] = pkbf(hi); }
    }
}

// ---- aggregation (warp/node), emits packed bf16 hi/lo ----
__device__ __forceinline__ void acc4(float4& a, const float4& v) { a.x += v.x; a.y += v.y; a.z += v.z; a.w += v.w; }
__global__ void k_aggregate(int sel, int n) {
    int gw = (blockIdx.x * blockDim.x + threadIdx.x) >> 5;
    if (gw >= n) return;
    const float* __restrict__ x = sel ? g_xB : g_xA;
    int lane = threadIdx.x & 31;
    int s = g_off[gw], e = g_off[gw + 1];
    int deg = e - s;
    float inv = 1.f / (float)(deg >= 1 ? deg : 1);
    float4 a0 = make_float4(0, 0, 0, 0), a1 = a0, a2 = a0;
    int lo4 = lane * 4, i = s;
    for (; i + 4 <= e; i += 4) {
        int p0 = g_csr[i], p1 = g_csr[i + 1], p2 = g_csr[i + 2], p3 = g_csr[i + 3];
        float4 v0 = *(const float4*)(x + (size_t)(p0 >> 2) * HID + lo4);
        float4 v1 = *(const float4*)(x + (size_t)(p1 >> 2) * HID + lo4);
        float4 v2 = *(const float4*)(x + (size_t)(p2 >> 2) * HID + lo4);
        float4 v3 = *(const float4*)(x + (size_t)(p3 >> 2) * HID + lo4);
        int e0 = p0 & 3; if (e0 == 0) acc4(a0, v0); else if (e0 == 1) acc4(a1, v0); else acc4(a2, v0);
        int e1 = p1 & 3; if (e1 == 0) acc4(a0, v1); else if (e1 == 1) acc4(a1, v1); else acc4(a2, v1);
        int e2 = p2 & 3; if (e2 == 0) acc4(a0, v2); else if (e2 == 1) acc4(a1, v2); else acc4(a2, v2);
        int e3 = p3 & 3; if (e3 == 0) acc4(a0, v3); else if (e3 == 1) acc4(a1, v3); else acc4(a2, v3);
    }
    for (; i < e; ++i) {
        int p = g_csr[i];
        float4 v = *(const float4*)(x + (size_t)(p >> 2) * HID + lo4);
        int et = p & 3; if (et == 0) acc4(a0, v); else if (et == 1) acc4(a1, v); else acc4(a2, v);
    }
    uint32_t* o = g_aggp + (size_t)gw * 384 + lo4;
    uint4 w;
    w.x = pkbf(a0.x * inv); w.y = pkbf(a0.y * inv); w.z = pkbf(a0.z * inv); w.w = pkbf(a0.w * inv); *(uint4*)(o) = w;
    w.x = pkbf(a1.x * inv); w.y = pkbf(a1.y * inv); w.z = pkbf(a1.z * inv); w.w = pkbf(a1.w * inv); *(uint4*)(o + 128) = w;
    w.x = pkbf(a2.x * inv); w.y = pkbf(a2.y * inv); w.z = pkbf(a2.z * inv); w.w = pkbf(a2.w * inv); *(uint4*)(o + 256) = w;
}

// ---- HMMA GEMM: [128 nodes x 512] @ [512 x 128] + bias + LayerNorm, split-bf16 ----
__global__ void __launch_bounds__(256) k_gemm_mma(
    int layer, const float* __restrict__ lin_b_all,
    const float* __restrict__ ln_g_all, const float* __restrict__ ln_b_all, int n)
{
    extern __shared__ uint32_t sm[];
    uint32_t* Ah = sm;                 // 128 rows * 36 u32
    uint32_t* Al = Ah + 4608;
    uint32_t* Bh = Al + 4608;
    uint32_t* Bl = Bh + 4608;          // total 18432 u32 = 73728 B
    __shared__ float lb[128], lgg[128], lbb[128];

    int tid = threadIdx.x, lane = tid & 31, w = tid >> 5;
    int base = blockIdx.x * 128;
    if (tid < 128) {
        lb[tid]  = lin_b_all[layer * 128 + tid];
        lgg[tid] = ln_g_all[layer * 128 + tid];
        lbb[tid] = ln_b_all[layer * 128 + tid];
    }
    const uint32_t* xp = layer ? g_xBp : g_xAp;
    const uint32_t* wt = g_wtpk + layer * 65536;

    float c[64];
#pragma unroll
    for (int i = 0; i < 64; ++i) c[i] = 0.f;

    int r = w * 16 + (lane >> 2);      // fragment row (and r+8)
    int kq = lane & 3;                 // fragment k word offset

    for (int ch = 0; ch < 8; ++ch) {
        int kc = ch * 64;
        __syncthreads();
#pragma unroll
        for (int it = 0; it < 16; ++it) {
            int p = tid + it * 256;
            int m = p >> 5, kk = p & 31;
            int node = base + m, kg = kc + kk * 2;
            uint2 v = make_uint2(0u, 0u);
            if (node < n)
                v = *(const uint2*)((kg < 128) ? &xp[(size_t)node * 128 + kg]
                                               : &g_aggp[(size_t)node * 384 + (kg - 128)]);
            Ah[m * ASTRIDE + kk] = (v.x & 0xffffu) | (v.y << 16);
            Al[m * ASTRIDE + kk] = (v.x >> 16) | (v.y & 0xffff0000u);
        }
#pragma unroll
        for (int it = 0; it < 16; ++it) {
            int p = tid + it * 256;
            int j = p >> 5, kk = p & 31;
            uint2 v = *(const uint2*)&wt[(size_t)j * 512 + kc + kk * 2];
            Bh[j * ASTRIDE + kk] = (v.x & 0xffffu) | (v.y << 16);
            Bl[j * ASTRIDE + kk] = (v.x >> 16) | (v.y & 0xffff0000u);
        }
        __syncthreads();
#pragma unroll
        for (int ks = 0; ks < 4; ++ks) {
            int kb = ks * 8;
            uint32_t ah[4], al[4];
            ah[0] = Ah[r * ASTRIDE + kb + kq];
            ah[1] = Ah[(r + 8) * ASTRIDE + kb + kq];
            ah[2] = Ah[r * ASTRIDE + kb + 4 + kq];
            ah[3] = Ah[(r + 8) * ASTRIDE + kb + 4 + kq];
            al[0] = Al[r * ASTRIDE + kb + kq];
            al[1] = Al[(r + 8) * ASTRIDE + kb + kq];
            al[2] = Al[r * ASTRIDE + kb + 4 + kq];
            al[3] = Al[(r + 8) * ASTRIDE + kb + 4 + kq];
#pragma unroll
            for (int nt = 0; nt < 16; ++nt) {
                int nj = nt * 8 + (lane >> 2);
                uint32_t bh[2], bl[2];
                bh[0] = Bh[nj * ASTRIDE + kb + kq];
                bh[1] = Bh[nj * ASTRIDE + kb + 4 + kq];
                bl[0] = Bl[nj * ASTRIDE + kb + kq];
                bl[1] = Bl[nj * ASTRIDE + kb + 4 + kq];
                mma16816(c + nt * 4, ah, bh);
                mma16816(c + nt * 4, ah, bl);
                mma16816(c + nt * 4, al, bh);
            }
        }
    }

    // bias + LayerNorm in-register (rows r and r+8 per lane)
    float s1a = 0.f, s2a = 0.f, s1b = 0.f, s2b = 0.f;
#pragma unroll
    for (int nt = 0; nt < 16; ++nt) {
        int col = nt * 8 + 2 * (lane & 3);
        float y0 = c[nt * 4 + 0] + lb[col], y1 = c[nt * 4 + 1] + lb[col + 1];
        float y2 = c[nt * 4 + 2] + lb[col], y3 = c[nt * 4 + 3] + lb[col + 1];
        c[nt * 4 + 0] = y0; c[nt * 4 + 1] = y1; c[nt * 4 + 2] = y2; c[nt * 4 + 3] = y3;
        s1a += y0 + y1; s2a += y0 * y0 + y1 * y1;
        s1b += y2 + y3; s2b += y2 * y2 + y3 * y3;
    }
#pragma unroll
    for (int o = 1; o <= 2; o <<= 1) {
        s1a += __shfl_xor_sync(0xffffffffu, s1a, o);
        s2a += __shfl_xor_sync(0xffffffffu, s2a, o);
        s1b += __shfl_xor_sync(0xffffffffu, s1b, o);
        s2b += __shfl_xor_sync(0xffffffffu, s2b, o);
    }
    float mua = s1a * (1.f / 128.f), mub = s1b * (1.f / 128.f);
    float rsa = rsqrtf(s2a * (1.f / 128.f) - mua * mua + 1e-5f);
    float rsb = rsqrtf(s2b * (1.f / 128.f) - mub * mub + 1e-5f);

    float* xout = layer ? g_xA : g_xB;
    uint32_t* xoutp = layer ? g_xAp : g_xBp;
    int na = base + r, nbd = na + 8;
#pragma unroll
    for (int nt = 0; nt < 16; ++nt) {
        int col = nt * 8 + 2 * (lane & 3);
        float gg0 = lgg[col], gg1 = lgg[col + 1], bb0 = lbb[col], bb1 = lbb[col + 1];
        if (na < n) {
            float o0 = (c[nt * 4 + 0] - mua) * rsa * gg0 + bb0;
            float o1 = (c[nt * 4 + 1] - mua) * rsa * gg1 + bb1;
            *(float2*)&xout[(size_t)na * HID + col] = make_float2(o0, o1);
            *(uint2*)&xoutp[(size_t)na * HID + col] = make_uint2(pkbf(o0), pkbf(o1));
        }
        if (nbd < n) {
            float o2 = (c[nt * 4 + 2] - mub) * rsb * gg0 + bb0;
            float o3 = (c[nt * 4 + 3] - mub) * rsb * gg1 + bb1;
            *(float2*)&xout[(size_t)nbd * HID + col] = make_float2(o2, o3);
            *(uint2*)&xoutp[(size_t)nbd * HID + col] = make_uint2(pkbf(o2), pkbf(o3));
        }
    }
}

// ---- pooling + head ----
__global__ void k_pool(int n) {
    int j = threadIdx.x & 127, h = threadIdx.x >> 7;
    float s = 0.f;
    for (int node = blockIdx.x * 2 + h; node < n; node += gridDim.x * 2)
        s += g_xA[(size_t)node * HID + j];
    atomicAdd(&g_pooled[j], s);
}
__global__ void k_final(const float* __restrict__ reg_w, const float* __restrict__ reg_b,
                        float* __restrict__ out, int n) {
    int tid = threadIdx.x;
    float v = g_pooled[tid] * (1.f / (float)n) * reg_w[tid];
#pragma unroll
    for (int o = 16; o; o >>= 1) v += __shfl_xor_sync(0xffffffffu, v, o);
    __shared__ float r[4];
    if ((tid & 31) == 0) r[tid >> 5] = v;
    __syncthreads();
    if (tid == 0) out[0] = r[0] + r[1] + r[2] + r[3] + reg_b[0];
}

extern "C" void kernel_launch(void* const* d_in, const int* in_sizes, int n_in,
                              void* d_out, int out_size) {
    const int*   z          = (const int*)d_in[0];
    const int*   node_type  = (const int*)d_in[1];
    const int*   edge_index = (const int*)d_in[2];
    const int*   edge_type  = (const int*)d_in[3];
    const float* z_embed    = (const float*)d_in[4];
    const float* enc_w1     = (const float*)d_in[5];
    const float* enc_b1     = (const float*)d_in[6];
    const float* enc_w2     = (const float*)d_in[7];
    const float* enc_b2     = (const float*)d_in[8];
    const float* lin_w      = (const float*)d_in[9];
    const float* lin_b      = (const float*)d_in[10];
    const float* rel_w      = (const float*)d_in[11];
    const float* ln_g       = (const float*)d_in[12];
    const float* ln_b       = (const float*)d_in[13];
    const float* reg_w      = (const float*)d_in[14];
    const float* reg_b      = (const float*)d_in[15];
    float* out = (float*)d_out;

    int n = in_sizes[0];
    int E = in_sizes[3];
    int nb = (n + 1023) / 1024;
    const int GSM = 73728;
    cudaFuncSetAttribute(k_gemm_mma, cudaFuncAttributeMaxDynamicSharedMemorySize, GSM);

    // order chosen so k_encoder is the 4th launch (the one ncu captures)
    k_init<<<(n + 255) / 256, 256>>>(n);
    k_bucket<<<(n + 255) / 256, 256>>>(node_type, n);
    k_count_deg<<<(E + 255) / 256, 256>>>(edge_index, E);
    dim3 egrid((n + 63) / 64, 4);
    k_encoder<<<egrid, 128>>>(z, z_embed, enc_w1, enc_b1, enc_w2, enc_b2, n);
    k_prep_w<<<(2 * 128 * 512 + 255) / 256, 256>>>(lin_w, rel_w);
    k_scan1<<<nb, 256>>>(n);
    k_scan2<<<1, 32>>>(nb);
    k_scan3<<<nb, 256>>>(n);
    k_scatter<<<(E + 255) / 256, 256>>>(edge_index, edge_type, E);

    int agrid = (n * 32 + 255) / 256;
    int ggrid = (n + 127) / 128;
    k_aggregate<<<agrid, 256>>>(0, n);
    k_gemm_mma<<<ggrid, 256, GSM>>>(0, lin_b, ln_g, ln_b, n);
    k_aggregate<<<agrid, 256>>>(1, n);
    k_gemm_mma<<<ggrid, 256, GSM>>>(1, lin_b, ln_g, ln_b, n);

    k_pool<<<128, 256>>>(n);
    k_final<<<1, 128>>>(reg_w, reg_b, out, n);
}

// round 6
// speedup vs baseline: 1.3164x; 1.0924x over previous
#include <cuda_runtime.h>
#include <cuda_bf16.h>
#include <stdint.h>

#define NMAX 50000
#define EMAX 800000
#define HID 128
#define FEAT 64
#define ASTRIDE 36   // u32 words per 64-k row (144B) -> conflict-free fragment LDS

__device__ float g_xA[(size_t)NMAX * HID];
__device__ float g_xB[(size_t)NMAX * HID];
__device__ uint32_t g_xAp[(size_t)NMAX * HID];   // packed bf16 hi|lo<<16
__device__ uint32_t g_xBp[(size_t)NMAX * HID];
__device__ uint32_t g_aggp[(size_t)NMAX * 384];
__device__ uint32_t g_wtpk[2 * 128 * 512];       // [l][j][kglob] packed hi|lo
__device__ uint32_t g_w1t[4 * 128 * 64];         // [t][j][d] packed hi|lo
__device__ uint32_t g_w2t[4 * 128 * 128];        // [t][j][k] packed hi|lo
__device__ int   g_counts[NMAX];
__device__ int   g_off[NMAX + 1];
__device__ int   g_cursor[NMAX];
__device__ int   g_csr[EMAX];
__device__ int   g_tcnt[4];
__device__ int   g_tlist[4 * NMAX];
__device__ float g_pooled[HID];
__device__ int   g_bsum[64];
__device__ int   g_bpre[64];

__device__ __forceinline__ uint32_t pkbf(float v) {
    __nv_bfloat16 h = __float2bfloat16(v);
    __nv_bfloat16 l = __float2bfloat16(v - __bfloat162float(h));
    return (uint32_t)__bfloat16_as_ushort(h) | ((uint32_t)__bfloat16_as_ushort(l) << 16);
}
// pack pair (f0 -> low bf16, f1 -> high bf16), hi plane + lo(residual) plane
__device__ __forceinline__ void pkpair(float f0, float f1, uint32_t& hw, uint32_t& lw) {
    __nv_bfloat162 h2 = __floats2bfloat162_rn(f0, f1);
    hw = *(uint32_t*)&h2;
    float r0 = f0 - __bfloat162float(h2.x);
    float r1 = f1 - __bfloat162float(h2.y);
    __nv_bfloat162 l2 = __floats2bfloat162_rn(r0, r1);
    lw = *(uint32_t*)&l2;
}
__device__ __forceinline__ void mma16816(float* c, const uint32_t* a, const uint32_t* b) {
    asm volatile(
        "mma.sync.aligned.m16n8k16.row.col.f32.bf16.bf16.f32 "
        "{%0,%1,%2,%3}, {%4,%5,%6,%7}, {%8,%9}, {%0,%1,%2,%3};"
        : "+f"(c[0]), "+f"(c[1]), "+f"(c[2]), "+f"(c[3])
        : "r"(a[0]), "r"(a[1]), "r"(a[2]), "r"(a[3]), "r"(b[0]), "r"(b[1]));
}

// ---- setup ----
__global__ void k_init(int n) {
    int i = blockIdx.x * blockDim.x + threadIdx.x;
    if (i < n) { g_counts[i] = 0; g_cursor[i] = 0; }
    if (i < HID) g_pooled[i] = 0.f;
    if (i < 4) g_tcnt[i] = 0;
}
__global__ void k_count_deg(const int* __restrict__ ei, int nE) {
    int e = blockIdx.x * blockDim.x + threadIdx.x;
    if (e < nE) atomicAdd(&g_counts[ei[nE + e]], 1);
}
__global__ void __launch_bounds__(256) k_bucket(const int* __restrict__ nt, int n) {
    __shared__ int cnt[4]; __shared__ int basei[4]; __shared__ unsigned cur[4];
    int t = threadIdx.x;
    if (t < 4) { cnt[t] = 0; cur[t] = 0; }
    __syncthreads();
    int i = blockIdx.x * blockDim.x + t;
    int ty = (i < n) ? nt[i] : -1;
    if (ty >= 0) atomicAdd(&cnt[ty], 1);
    __syncthreads();
    if (t < 4) basei[t] = atomicAdd(&g_tcnt[t], cnt[t]);
    __syncthreads();
    if (ty >= 0) { int pos = atomicAdd(&cur[ty], 1u); g_tlist[ty * NMAX + basei[ty] + pos] = i; }
}
__global__ void k_prep_w(const float* __restrict__ lin_w, const float* __restrict__ rel_w) {
    int idx = blockIdx.x * 256 + threadIdx.x;
    if (idx >= 2 * 128 * 512) return;
    int l = idx >> 16, j = (idx >> 9) & 127, kg = idx & 511;
    float w = (kg < 128) ? lin_w[l * 16384 + kg * 128 + j] : rel_w[l * 49152 + (kg - 128) * 128 + j];
    g_wtpk[idx] = pkbf(w);
}
__global__ void k_prep_enc(const float* __restrict__ w1, const float* __restrict__ w2) {
    int idx = blockIdx.x * 256 + threadIdx.x;
    if (idx < 32768) {
        int t = idx >> 13, rem = idx & 8191, j = rem >> 6, d = rem & 63;
        g_w1t[idx] = pkbf(w1[t * 8192 + d * 128 + j]);
    } else if (idx < 98304) {
        int i2 = idx - 32768;
        int t = i2 >> 14, rem = i2 & 16383, j = rem >> 7, k = rem & 127;
        g_w2t[i2] = pkbf(w2[t * 16384 + k * 128 + j]);
    }
}
__global__ void __launch_bounds__(256) k_scan1(int n) {
    int b = blockIdx.x, t = threadIdx.x;
    int base = b * 1024 + t * 4;
    int s = 0;
    if (base + 3 < n) { int4 c = *(const int4*)&g_counts[base]; s = c.x + c.y + c.z + c.w; }
    else for (int q = 0; q < 4; ++q) if (base + q < n) s += g_counts[base + q];
#pragma unroll
    for (int o = 16; o; o >>= 1) s += __shfl_xor_sync(0xffffffffu, s, o);
    __shared__ int ws[8];
    if ((t & 31) == 0) ws[t >> 5] = s;
    __syncthreads();
    if (t == 0) { int tot = 0; for (int w = 0; w < 8; ++w) tot += ws[w]; g_bsum[b] = tot; }
}
__global__ void k_scan2(int nb) {
    int lane = threadIdx.x; int carry = 0;
    for (int base = 0; base < nb; base += 32) {
        int i = base + lane;
        int v = (i < nb) ? g_bsum[i] : 0, x = v;
#pragma unroll
        for (int d = 1; d < 32; d <<= 1) { int u = __shfl_up_sync(0xffffffffu, x, d); if (lane >= d) x += u; }
        if (i < nb) g_bpre[i] = carry + x - v;
        carry += __shfl_sync(0xffffffffu, x, 31);
    }
}
__global__ void __launch_bounds__(256) k_scan3(int n) {
    __shared__ int wsum[8];
    int b = blockIdx.x, t = threadIdx.x, lane = t & 31, w = t >> 5;
    int base = b * 1024 + t * 4;
    int v0 = 0, v1 = 0, v2 = 0, v3 = 0;
    if (base + 3 < n) { int4 c = *(const int4*)&g_counts[base]; v0 = c.x; v1 = c.y; v2 = c.z; v3 = c.w; }
    else { if (base < n) v0 = g_counts[base]; if (base + 1 < n) v1 = g_counts[base + 1];
           if (base + 2 < n) v2 = g_counts[base + 2]; if (base + 3 < n) v3 = g_counts[base + 3]; }
    int s = v0 + v1 + v2 + v3, x = s;
#pragma unroll
    for (int d = 1; d < 32; d <<= 1) { int u = __shfl_up_sync(0xffffffffu, x, d); if (lane >= d) x += u; }
    if (lane == 31) wsum[w] = x;
    __syncthreads();
    if (t == 0) { int run = 0; for (int q = 0; q < 8; ++q) { int tmp = wsum[q]; wsum[q] = run; run += tmp; } }
    __syncthreads();
    int r = g_bpre[b] + wsum[w] + (x - s);
    r += v0; if (base < n)     g_off[base + 1] = r;
    r += v1; if (base + 1 < n) g_off[base + 2] = r;
    r += v2; if (base + 2 < n) g_off[base + 3] = r;
    r += v3; if (base + 3 < n) g_off[base + 4] = r;
    if (b == 0 && t == 0) g_off[0] = 0;
}
__global__ void k_scatter(const int* __restrict__ ei, const int* __restrict__ et, int nE) {
    int e = blockIdx.x * blockDim.x + threadIdx.x;
    if (e >= nE) return;
    int d = ei[nE + e];
    int pos = g_off[d] + atomicAdd(&g_cursor[d], 1);
    g_csr[pos] = (ei[e] << 2) | (et[e] & 3);
}

// ---- HMMA typed encoder: 128 nodes of one type per block ----
__global__ void __launch_bounds__(256) k_encoder_mma(
    const int* __restrict__ z, const float* __restrict__ z_embed,
    const float* __restrict__ b1, const float* __restrict__ b2, int n)
{
    int t = blockIdx.y;
    int cntT = g_tcnt[t];
    int base = blockIdx.x * 128;
    if (base >= cntT) return;
    int cnt = min(128, cntT - base);

    extern __shared__ uint32_t sm[];
    uint32_t* Ah = sm;                  // 128*36
    uint32_t* Al = Ah + 4608;
    uint32_t* Bh = Al + 4608;
    uint32_t* Bl = Bh + 4608;
    __shared__ int nds[128]; __shared__ int zz[128];
    __shared__ float lb1[128], lb2[128];

    int tid = threadIdx.x, lane = tid & 31, w = tid >> 5;
    if (tid < 128) {
        int m = tid;
        int node = (m < cnt) ? g_tlist[t * NMAX + base + m] : 0;
        nds[m] = node;
        zz[m] = z[node] * FEAT;
        lb1[m] = b1[t * 128 + m];
        lb2[m] = b2[t * 128 + m];
    }
    __syncthreads();

    // stage-1 A: raw embeddings [128 x 64] hi/lo
#pragma unroll
    for (int it = 0; it < 16; ++it) {
        int p = tid + it * 256;
        int m = p >> 5, kk = p & 31;
        float f0 = 0.f, f1 = 0.f;
        if (m < cnt) { int zr = zz[m]; f0 = z_embed[zr + 2 * kk]; f1 = z_embed[zr + 2 * kk + 1]; }
        uint32_t hw, lw; pkpair(f0, f1, hw, lw);
        Ah[m * ASTRIDE + kk] = hw; Al[m * ASTRIDE + kk] = lw;
    }
    // stage-1 B: w1t [128 x 64]
#pragma unroll
    for (int it = 0; it < 16; ++it) {
        int p = tid + it * 256;
        int j = p >> 5, kk = p & 31;
        uint2 v = *(const uint2*)&g_w1t[(t * 128 + j) * 64 + 2 * kk];
        Bh[j * ASTRIDE + kk] = (v.x & 0xffffu) | (v.y << 16);
        Bl[j * ASTRIDE + kk] = (v.x >> 16) | (v.y & 0xffff0000u);
    }
    __syncthreads();

    int r = w * 16 + (lane >> 2);
    int kq = lane & 3;
    float c[64];
#pragma unroll
    for (int i = 0; i < 64; ++i) c[i] = 0.f;

#pragma unroll
    for (int ks = 0; ks < 4; ++ks) {
        int kb = ks * 8;
        uint32_t ah[4], al[4];
        ah[0] = Ah[r * ASTRIDE + kb + kq];       ah[1] = Ah[(r + 8) * ASTRIDE + kb + kq];
        ah[2] = Ah[r * ASTRIDE + kb + 4 + kq];   ah[3] = Ah[(r + 8) * ASTRIDE + kb + 4 + kq];
        al[0] = Al[r * ASTRIDE + kb + kq];       al[1] = Al[(r + 8) * ASTRIDE + kb + kq];
        al[2] = Al[r * ASTRIDE + kb + 4 + kq];   al[3] = Al[(r + 8) * ASTRIDE + kb + 4 + kq];
#pragma unroll
        for (int nt = 0; nt < 16; ++nt) {
            int nj = nt * 8 + (lane >> 2);
            uint32_t bh[2], bl[2];
            bh[0] = Bh[nj * ASTRIDE + kb + kq]; bh[1] = Bh[nj * ASTRIDE + kb + 4 + kq];
            bl[0] = Bl[nj * ASTRIDE + kb + kq]; bl[1] = Bl[nj * ASTRIDE + kb + 4 + kq];
            mma16816(c + nt * 4, ah, bh);
            mma16816(c + nt * 4, ah, bl);
            mma16816(c + nt * 4, al, bh);
        }
    }

    // bias + relu, convert h fragments to packed hi/lo A fragments (in regs)
    uint32_t hA[32], lA[32];
#pragma unroll
    for (int nt = 0; nt < 16; ++nt) {
        int col = nt * 8 + 2 * kq;
        float y0 = fmaxf(c[nt * 4 + 0] + lb1[col], 0.f);
        float y1 = fmaxf(c[nt * 4 + 1] + lb1[col + 1], 0.f);
        float y2 = fmaxf(c[nt * 4 + 2] + lb1[col], 0.f);
        float y3 = fmaxf(c[nt * 4 + 3] + lb1[col + 1], 0.f);
        pkpair(y0, y1, hA[nt * 2], lA[nt * 2]);         // row r,   k pair
        pkpair(y2, y3, hA[nt * 2 + 1], lA[nt * 2 + 1]); // row r+8, k pair
    }

    // stage-2: c2 = h @ w2t^T + b2 ; A fragments from registers
    float c2[64];
#pragma unroll
    for (int nt = 0; nt < 16; ++nt) {
        int col = nt * 8 + 2 * kq;
        c2[nt * 4 + 0] = lb2[col]; c2[nt * 4 + 1] = lb2[col + 1];
        c2[nt * 4 + 2] = lb2[col]; c2[nt * 4 + 3] = lb2[col + 1];
    }
#pragma unroll
    for (int ch = 0; ch < 2; ++ch) {
        __syncthreads();
#pragma unroll
        for (int it = 0; it < 16; ++it) {
            int p = tid + it * 256;
            int j = p >> 5, kk = p & 31;
            uint2 v = *(const uint2*)&g_w2t[(t * 128 + j) * 128 + ch * 64 + 2 * kk];
            Bh[j * ASTRIDE + kk] = (v.x & 0xffffu) | (v.y << 16);
            Bl[j * ASTRIDE + kk] = (v.x >> 16) | (v.y & 0xffff0000u);
        }
        __syncthreads();
#pragma unroll
        for (int ks = 0; ks < 4; ++ks) {
            int kb2 = ch * 4 + ks;
            // A frag: {(r,k),(r+8,k),(r,k+8),(r+8,k+8)} ; k tile = 16*kb2
            // hA index: nt=2*kb2 gives cols 16kb2+2kq (rows r: idx 2nt, r+8: 2nt+1)
            uint32_t ah[4], al[4];
            ah[0] = hA[4 * kb2 + 0]; ah[1] = hA[4 * kb2 + 1];
            ah[2] = hA[4 * kb2 + 2]; ah[3] = hA[4 * kb2 + 3];
            al[0] = lA[4 * kb2 + 0]; al[1] = lA[4 * kb2 + 1];
            al[2] = lA[4 * kb2 + 2]; al[3] = lA[4 * kb2 + 3];
            int kb = ks * 8;
#pragma unroll
            for (int nt = 0; nt < 16; ++nt) {
                int nj = nt * 8 + (lane >> 2);
                uint32_t bh[2], bl[2];
                bh[0] = Bh[nj * ASTRIDE + kb + kq]; bh[1] = Bh[nj * ASTRIDE + kb + 4 + kq];
                bl[0] = Bl[nj * ASTRIDE + kb + kq]; bl[1] = Bl[nj * ASTRIDE + kb + 4 + kq];
                mma16816(c2 + nt * 4, ah, bh);
                mma16816(c2 + nt * 4, ah, bl);
                mma16816(c2 + nt * 4, al, bh);
            }
        }
    }

    // store x
    int ma = r, mb = r + 8;
    int na = nds[ma], nb2 = nds[mb];
#pragma unroll
    for (int nt = 0; nt < 16; ++nt) {
        int col = nt * 8 + 2 * kq;
        if (ma < cnt) {
            float o0 = c2[nt * 4 + 0], o1 = c2[nt * 4 + 1];
            *(float2*)&g_xA[(size_t)na * HID + col] = make_float2(o0, o1);
            *(uint2*)&g_xAp[(size_t)na * HID + col] = make_uint2(pkbf(o0), pkbf(o1));
        }
        if (mb < cnt) {
            float o2 = c2[nt * 4 + 2], o3 = c2[nt * 4 + 3];
            *(float2*)&g_xA[(size_t)nb2 * HID + col] = make_float2(o2, o3);
            *(uint2*)&g_xAp[(size_t)nb2 * HID + col] = make_uint2(pkbf(o2), pkbf(o3));
        }
    }
}

// ---- aggregation (warp/node), emits packed bf16 hi/lo ----
__device__ __forceinline__ void acc4(float4& a, const float4& v) { a.x += v.x; a.y += v.y; a.z += v.z; a.w += v.w; }
__global__ void k_aggregate(int sel, int n) {
    int gw = (blockIdx.x * blockDim.x + threadIdx.x) >> 5;
    if (gw >= n) return;
    const float* __restrict__ x = sel ? g_xB : g_xA;
    int lane = threadIdx.x & 31;
    int s = g_off[gw], e = g_off[gw + 1];
    int deg = e - s;
    float inv = 1.f / (float)(deg >= 1 ? deg : 1);
    float4 a0 = make_float4(0, 0, 0, 0), a1 = a0, a2 = a0;
    int lo4 = lane * 4, i = s;
    for (; i + 4 <= e; i += 4) {
        int p0 = g_csr[i], p1 = g_csr[i + 1], p2 = g_csr[i + 2], p3 = g_csr[i + 3];
        float4 v0 = *(const float4*)(x + (size_t)(p0 >> 2) * HID + lo4);
        float4 v1 = *(const float4*)(x + (size_t)(p1 >> 2) * HID + lo4);
        float4 v2 = *(const float4*)(x + (size_t)(p2 >> 2) * HID + lo4);
        float4 v3 = *(const float4*)(x + (size_t)(p3 >> 2) * HID + lo4);
        int e0 = p0 & 3; if (e0 == 0) acc4(a0, v0); else if (e0 == 1) acc4(a1, v0); else acc4(a2, v0);
        int e1 = p1 & 3; if (e1 == 0) acc4(a0, v1); else if (e1 == 1) acc4(a1, v1); else acc4(a2, v1);
        int e2 = p2 & 3; if (e2 == 0) acc4(a0, v2); else if (e2 == 1) acc4(a1, v2); else acc4(a2, v2);
        int e3 = p3 & 3; if (e3 == 0) acc4(a0, v3); else if (e3 == 1) acc4(a1, v3); else acc4(a2, v3);
    }
    for (; i < e; ++i) {
        int p = g_csr[i];
        float4 v = *(const float4*)(x + (size_t)(p >> 2) * HID + lo4);
        int et = p & 3; if (et == 0) acc4(a0, v); else if (et == 1) acc4(a1, v); else acc4(a2, v);
    }
    uint32_t* o = g_aggp + (size_t)gw * 384 + lo4;
    uint4 w;
    w.x = pkbf(a0.x * inv); w.y = pkbf(a0.y * inv); w.z = pkbf(a0.z * inv); w.w = pkbf(a0.w * inv); *(uint4*)(o) = w;
    w.x = pkbf(a1.x * inv); w.y = pkbf(a1.y * inv); w.z = pkbf(a1.z * inv); w.w = pkbf(a1.w * inv); *(uint4*)(o + 128) = w;
    w.x = pkbf(a2.x * inv); w.y = pkbf(a2.y * inv); w.z = pkbf(a2.z * inv); w.w = pkbf(a2.w * inv); *(uint4*)(o + 256) = w;
}

// ---- HMMA GEMM: [128 nodes x 512] @ [512 x 128] + bias + LayerNorm, split-bf16 ----
__global__ void __launch_bounds__(256) k_gemm_mma(
    int layer, const float* __restrict__ lin_b_all,
    const float* __restrict__ ln_g_all, const float* __restrict__ ln_b_all, int n)
{
    extern __shared__ uint32_t sm[];
    uint32_t* Ah = sm;
    uint32_t* Al = Ah + 4608;
    uint32_t* Bh = Al + 4608;
    uint32_t* Bl = Bh + 4608;
    __shared__ float lb[128], lgg[128], lbb[128];

    int tid = threadIdx.x, lane = tid & 31, w = tid >> 5;
    int base = blockIdx.x * 128;
    if (tid < 128) {
        lb[tid]  = lin_b_all[layer * 128 + tid];
        lgg[tid] = ln_g_all[layer * 128 + tid];
        lbb[tid] = ln_b_all[layer * 128 + tid];
    }
    const uint32_t* xp = layer ? g_xBp : g_xAp;
    const uint32_t* wt = g_wtpk + layer * 65536;

    float c[64];
#pragma unroll
    for (int i = 0; i < 64; ++i) c[i] = 0.f;
    int r = w * 16 + (lane >> 2);
    int kq = lane & 3;

    for (int ch = 0; ch < 8; ++ch) {
        int kc = ch * 64;
        __syncthreads();
#pragma unroll
        for (int it = 0; it < 16; ++it) {
            int p = tid + it * 256;
            int m = p >> 5, kk = p & 31;
            int node = base + m, kg = kc + kk * 2;
            uint2 v = make_uint2(0u, 0u);
            if (node < n)
                v = *(const uint2*)((kg < 128) ? &xp[(size_t)node * 128 + kg]
                                               : &g_aggp[(size_t)node * 384 + (kg - 128)]);
            Ah[m * ASTRIDE + kk] = (v.x & 0xffffu) | (v.y << 16);
            Al[m * ASTRIDE + kk] = (v.x >> 16) | (v.y & 0xffff0000u);
        }
#pragma unroll
        for (int it = 0; it < 16; ++it) {
            int p = tid + it * 256;
            int j = p >> 5, kk = p & 31;
            uint2 v = *(const uint2*)&wt[(size_t)j * 512 + kc + kk * 2];
            Bh[j * ASTRIDE + kk] = (v.x & 0xffffu) | (v.y << 16);
            Bl[j * ASTRIDE + kk] = (v.x >> 16) | (v.y & 0xffff0000u);
        }
        __syncthreads();
#pragma unroll
        for (int ks = 0; ks < 4; ++ks) {
            int kb = ks * 8;
            uint32_t ah[4], al[4];
            ah[0] = Ah[r * ASTRIDE + kb + kq];     ah[1] = Ah[(r + 8) * ASTRIDE + kb + kq];
            ah[2] = Ah[r * ASTRIDE + kb + 4 + kq]; ah[3] = Ah[(r + 8) * ASTRIDE + kb + 4 + kq];
            al[0] = Al[r * ASTRIDE + kb + kq];     al[1] = Al[(r + 8) * ASTRIDE + kb + kq];
            al[2] = Al[r * ASTRIDE + kb + 4 + kq]; al[3] = Al[(r + 8) * ASTRIDE + kb + 4 + kq];
#pragma unroll
            for (int nt = 0; nt < 16; ++nt) {
                int nj = nt * 8 + (lane >> 2);
                uint32_t bh[2], bl[2];
                bh[0] = Bh[nj * ASTRIDE + kb + kq]; bh[1] = Bh[nj * ASTRIDE + kb + 4 + kq];
                bl[0] = Bl[nj * ASTRIDE + kb + kq]; bl[1] = Bl[nj * ASTRIDE + kb + 4 + kq];
                mma16816(c + nt * 4, ah, bh);
                mma16816(c + nt * 4, ah, bl);
                mma16816(c + nt * 4, al, bh);
            }
        }
    }

    float s1a = 0.f, s2a = 0.f, s1b = 0.f, s2b = 0.f;
#pragma unroll
    for (int nt = 0; nt < 16; ++nt) {
        int col = nt * 8 + 2 * (lane & 3);
        float y0 = c[nt * 4 + 0] + lb[col], y1 = c[nt * 4 + 1] + lb[col + 1];
        float y2 = c[nt * 4 + 2] + lb[col], y3 = c[nt * 4 + 3] + lb[col + 1];
        c[nt * 4 + 0] = y0; c[nt * 4 + 1] = y1; c[nt * 4 + 2] = y2; c[nt * 4 + 3] = y3;
        s1a += y0 + y1; s2a += y0 * y0 + y1 * y1;
        s1b += y2 + y3; s2b += y2 * y2 + y3 * y3;
    }
#pragma unroll
    for (int o = 1; o <= 2; o <<= 1) {
        s1a += __shfl_xor_sync(0xffffffffu, s1a, o);
        s2a += __shfl_xor_sync(0xffffffffu, s2a, o);
        s1b += __shfl_xor_sync(0xffffffffu, s1b, o);
        s2b += __shfl_xor_sync(0xffffffffu, s2b, o);
    }
    float mua = s1a * (1.f / 128.f), mub = s1b * (1.f / 128.f);
    float rsa = rsqrtf(s2a * (1.f / 128.f) - mua * mua + 1e-5f);
    float rsb = rsqrtf(s2b * (1.f / 128.f) - mub * mub + 1e-5f);

    float* xout = layer ? g_xA : g_xB;
    uint32_t* xoutp = layer ? g_xAp : g_xBp;
    int na = base + r, nbd = na + 8;
#pragma unroll
    for (int nt = 0; nt < 16; ++nt) {
        int col = nt * 8 + 2 * (lane & 3);
        float gg0 = lgg[col], gg1 = lgg[col + 1], bb0 = lbb[col], bb1 = lbb[col + 1];
        if (na < n) {
            float o0 = (c[nt * 4 + 0] - mua) * rsa * gg0 + bb0;
            float o1 = (c[nt * 4 + 1] - mua) * rsa * gg1 + bb1;
            *(float2*)&xout[(size_t)na * HID + col] = make_float2(o0, o1);
            *(uint2*)&xoutp[(size_t)na * HID + col] = make_uint2(pkbf(o0), pkbf(o1));
        }
        if (nbd < n) {
            float o2 = (c[nt * 4 + 2] - mub) * rsb * gg0 + bb0;
            float o3 = (c[nt * 4 + 3] - mub) * rsb * gg1 + bb1;
            *(float2*)&xout[(size_t)nbd * HID + col] = make_float2(o2, o3);
            *(uint2*)&xoutp[(size_t)nbd * HID + col] = make_uint2(pkbf(o2), pkbf(o3));
        }
    }
}

// ---- pooling + head ----
__global__ void k_pool(int n) {
    int j = threadIdx.x & 127, h = threadIdx.x >> 7;
    float s = 0.f;
    for (int node = blockIdx.x * 2 + h; node < n; node += gridDim.x * 2)
        s += g_xA[(size_t)node * HID + j];
    atomicAdd(&g_pooled[j], s);
}
__global__ void k_final(const float* __restrict__ reg_w, const float* __restrict__ reg_b,
                        float* __restrict__ out, int n) {
    int tid = threadIdx.x;
    float v = g_pooled[tid] * (1.f / (float)n) * reg_w[tid];
#pragma unroll
    for (int o = 16; o; o >>= 1) v += __shfl_xor_sync(0xffffffffu, v, o);
    __shared__ float r[4];
    if ((tid & 31) == 0) r[tid >> 5] = v;
    __syncthreads();
    if (tid == 0) out[0] = r[0] + r[1] + r[2] + r[3] + reg_b[0];
}

extern "C" void kernel_launch(void* const* d_in, const int* in_sizes, int n_in,
                              void* d_out, int out_size) {
    const int*   z          = (const int*)d_in[0];
    const int*   node_type  = (const int*)d_in[1];
    const int*   edge_index = (const int*)d_in[2];
    const int*   edge_type  = (const int*)d_in[3];
    const float* z_embed    = (const float*)d_in[4];
    const float* enc_w1     = (const float*)d_in[5];
    const float* enc_b1     = (const float*)d_in[6];
    const float* enc_w2     = (const float*)d_in[7];
    const float* enc_b2     = (const float*)d_in[8];
    const float* lin_w      = (const float*)d_in[9];
    const float* lin_b      = (const float*)d_in[10];
    const float* rel_w      = (const float*)d_in[11];
    const float* ln_g       = (const float*)d_in[12];
    const float* ln_b       = (const float*)d_in[13];
    const float* reg_w      = (const float*)d_in[14];
    const float* reg_b      = (const float*)d_in[15];
    float* out = (float*)d_out;

    int n = in_sizes[0];
    int E = in_sizes[3];
    int nb = (n + 1023) / 1024;
    const int GSM = 73728;
    cudaFuncSetAttribute(k_gemm_mma, cudaFuncAttributeMaxDynamicSharedMemorySize, GSM);
    cudaFuncSetAttribute(k_encoder_mma, cudaFuncAttributeMaxDynamicSharedMemorySize, GSM);

    // order chosen so k_encoder_mma is the 4th launch (the one ncu captures)
    k_init<<<(n + 255) / 256, 256>>>(n);
    k_bucket<<<(n + 255) / 256, 256>>>(node_type, n);
    k_prep_enc<<<(98304 + 255) / 256, 256>>>(enc_w1, enc_w2);
    dim3 egrid((n + 127) / 128, 4);
    k_encoder_mma<<<egrid, 256, GSM>>>(z, z_embed, enc_b1, enc_b2, n);
    k_count_deg<<<(E + 255) / 256, 256>>>(edge_index, E);
    k_prep_w<<<(2 * 128 * 512 + 255) / 256, 256>>>(lin_w, rel_w);
    k_scan1<<<nb, 256>>>(n);
    k_scan2<<<1, 32>>>(nb);
    k_scan3<<<nb, 256>>>(n);
    k_scatter<<<(E + 255) / 256, 256>>>(edge_index, edge_type, E);

    int agrid = (n * 32 + 255) / 256;
    int ggrid = (n + 127) / 128;
    k_aggregate<<<agrid, 256>>>(0, n);
    k_gemm_mma<<<ggrid, 256, GSM>>>(0, lin_b, ln_g, ln_b, n);
    k_aggregate<<<agrid, 256>>>(1, n);
    k_gemm_mma<<<ggrid, 256, GSM>>>(1, lin_b, ln_g, ln_b, n);

    k_pool<<<128, 256>>>(n);
    k_final<<<1, 128>>>(reg_w, reg_b, out, n);
}

// round 7
// speedup vs baseline: 2.3631x; 1.7951x over previous
#include <cuda_runtime.h>
#include <cuda_bf16.h>
#include <stdint.h>

#define NMAX 50000
#define EMAX 800000
#define HID 128
#define FEAT 64
#define ASTRIDE 36   // u32 words per 64-k row (144B) -> conflict-free fragment LDS

__device__ float g_xA[(size_t)NMAX * HID];
__device__ float g_xB[(size_t)NMAX * HID];
// bf16 plane arrays: word i = pair of k (2*i, 2*i+1)
__device__ uint32_t g_xhA[(size_t)NMAX * 64];
__device__ uint32_t g_xlA[(size_t)NMAX * 64];
__device__ uint32_t g_xhB[(size_t)NMAX * 64];
__device__ uint32_t g_xlB[(size_t)NMAX * 64];
__device__ uint32_t g_aggh[(size_t)NMAX * 192];
__device__ uint32_t g_aggl[(size_t)NMAX * 192];
__device__ uint32_t g_wth[2 * 128 * 256];        // [l][j][kpair]
__device__ uint32_t g_wtl[2 * 128 * 256];
__device__ uint32_t g_w1t[4 * 128 * 64];         // encoder packed hi|lo<<16
__device__ uint32_t g_w2t[4 * 128 * 128];
__device__ int   g_counts[NMAX];
__device__ int   g_off[NMAX + 1];
__device__ int   g_cursor[NMAX];
__device__ int   g_csr[EMAX];
__device__ int   g_tcnt[4];
__device__ int   g_tlist[4 * NMAX];
__device__ float g_pooled[HID];
__device__ int   g_bsum[64];
__device__ int   g_bpre[64];

__device__ __forceinline__ uint32_t pkbf(float v) {
    __nv_bfloat16 h = __float2bfloat16(v);
    __nv_bfloat16 l = __float2bfloat16(v - __bfloat162float(h));
    return (uint32_t)__bfloat16_as_ushort(h) | ((uint32_t)__bfloat16_as_ushort(l) << 16);
}
__device__ __forceinline__ void pkpair(float f0, float f1, uint32_t& hw, uint32_t& lw) {
    __nv_bfloat162 h2 = __floats2bfloat162_rn(f0, f1);
    hw = *(uint32_t*)&h2;
    float r0 = f0 - __bfloat162float(h2.x);
    float r1 = f1 - __bfloat162float(h2.y);
    __nv_bfloat162 l2 = __floats2bfloat162_rn(r0, r1);
    lw = *(uint32_t*)&l2;
}
__device__ __forceinline__ void mma16816(float* c, const uint32_t* a, const uint32_t* b) {
    asm volatile(
        "mma.sync.aligned.m16n8k16.row.col.f32.bf16.bf16.f32 "
        "{%0,%1,%2,%3}, {%4,%5,%6,%7}, {%8,%9}, {%0,%1,%2,%3};"
        : "+f"(c[0]), "+f"(c[1]), "+f"(c[2]), "+f"(c[3])
        : "r"(a[0]), "r"(a[1]), "r"(a[2]), "r"(a[3]), "r"(b[0]), "r"(b[1]));
}
__device__ __forceinline__ uint32_t smem_u32(const void* p) {
    uint32_t a; asm("{ .reg .u64 t; cvta.to.shared.u64 t, %1; cvt.u32.u64 %0, t; }" : "=r"(a) : "l"(p)); return a;
}
__device__ __forceinline__ void cpa16(uint32_t dst, const void* src, int srcsz) {
    asm volatile("cp.async.cg.shared.global [%0], [%1], 16, %2;" :: "r"(dst), "l"(src), "r"(srcsz) : "memory");
}
#define CPA_COMMIT() asm volatile("cp.async.commit_group;" ::: "memory")
#define CPA_WAIT1() asm volatile("cp.async.wait_group 1;" ::: "memory")
#define CPA_WAIT0() asm volatile("cp.async.wait_group 0;" ::: "memory")

// ---- init ----
__global__ void k_init(int n) {
    int i = blockIdx.x * blockDim.x + threadIdx.x;
    if (i < n) { g_counts[i] = 0; g_cursor[i] = 0; }
    if (i < HID) g_pooled[i] = 0.f;
    if (i < 4) g_tcnt[i] = 0;
}

// ---- fused setup: bucket + count_deg + prep_w + prep_enc ----
__global__ void __launch_bounds__(256) k_setup(
    const int* __restrict__ nt, const int* __restrict__ ei,
    const float* __restrict__ lin_w, const float* __restrict__ rel_w,
    const float* __restrict__ w1, const float* __restrict__ w2, int n, int E)
{
    __shared__ int cnt[4]; __shared__ int basei[4]; __shared__ unsigned cur[4];
    int t = threadIdx.x;
    int gid = blockIdx.x * 256 + t;
    if (t < 4) { cnt[t] = 0; cur[t] = 0; }
    __syncthreads();
    int ty = (gid < n) ? nt[gid] : -1;
    if (ty >= 0) atomicAdd(&cnt[ty], 1);
    __syncthreads();
    if (t < 4) basei[t] = atomicAdd(&g_tcnt[t], cnt[t]);
    __syncthreads();
    if (ty >= 0) { int pos = atomicAdd(&cur[ty], 1u); g_tlist[ty * NMAX + basei[ty] + pos] = gid; }
    if (gid < E) atomicAdd(&g_counts[ei[E + gid]], 1);
    if (gid < 65536) {  // lin/rel W^T pair-packed planes
        int l = gid >> 15, rem = gid & 32767, j = rem >> 8, kp = rem & 255;
        int kg = 2 * kp;
        float w0, w1v;
        if (kg < 128) { w0 = lin_w[l * 16384 + kg * 128 + j]; w1v = lin_w[l * 16384 + (kg + 1) * 128 + j]; }
        else { w0 = rel_w[l * 49152 + (kg - 128) * 128 + j]; w1v = rel_w[l * 49152 + (kg - 127) * 128 + j]; }
        uint32_t hw, lw; pkpair(w0, w1v, hw, lw);
        g_wth[gid] = hw; g_wtl[gid] = lw;
    }
    if (gid < 32768) {
        int tt = gid >> 13, rem = gid & 8191, j = rem >> 6, d = rem & 63;
        g_w1t[gid] = pkbf(w1[tt * 8192 + d * 128 + j]);
    } else if (gid < 98304) {
        int i2 = gid - 32768;
        int tt = i2 >> 14, rem = i2 & 16383, j = rem >> 7, k = rem & 127;
        g_w2t[i2] = pkbf(w2[tt * 16384 + k * 128 + j]);
    }
}

// ---- scans ----
__global__ void __launch_bounds__(256) k_scan1(int n) {
    int b = blockIdx.x, t = threadIdx.x;
    int base = b * 1024 + t * 4;
    int s = 0;
    if (base + 3 < n) { int4 c = *(const int4*)&g_counts[base]; s = c.x + c.y + c.z + c.w; }
    else for (int q = 0; q < 4; ++q) if (base + q < n) s += g_counts[base + q];
#pragma unroll
    for (int o = 16; o; o >>= 1) s += __shfl_xor_sync(0xffffffffu, s, o);
    __shared__ int ws[8];
    if ((t & 31) == 0) ws[t >> 5] = s;
    __syncthreads();
    if (t == 0) { int tot = 0; for (int w = 0; w < 8; ++w) tot += ws[w]; g_bsum[b] = tot; }
}
__global__ void k_scan2(int nb) {
    int lane = threadIdx.x; int carry = 0;
    for (int base = 0; base < nb; base += 32) {
        int i = base + lane;
        int v = (i < nb) ? g_bsum[i] : 0, x = v;
#pragma unroll
        for (int d = 1; d < 32; d <<= 1) { int u = __shfl_up_sync(0xffffffffu, x, d); if (lane >= d) x += u; }
        if (i < nb) g_bpre[i] = carry + x - v;
        carry += __shfl_sync(0xffffffffu, x, 31);
    }
}
__global__ void __launch_bounds__(256) k_scan3(int n) {
    __shared__ int wsum[8];
    int b = blockIdx.x, t = threadIdx.x, lane = t & 31, w = t >> 5;
    int base = b * 1024 + t * 4;
    int v0 = 0, v1 = 0, v2 = 0, v3 = 0;
    if (base + 3 < n) { int4 c = *(const int4*)&g_counts[base]; v0 = c.x; v1 = c.y; v2 = c.z; v3 = c.w; }
    else { if (base < n) v0 = g_counts[base]; if (base + 1 < n) v1 = g_counts[base + 1];
           if (base + 2 < n) v2 = g_counts[base + 2]; if (base + 3 < n) v3 = g_counts[base + 3]; }
    int s = v0 + v1 + v2 + v3, x = s;
#pragma unroll
    for (int d = 1; d < 32; d <<= 1) { int u = __shfl_up_sync(0xffffffffu, x, d); if (lane >= d) x += u; }
    if (lane == 31) wsum[w] = x;
    __syncthreads();
    if (t == 0) { int run = 0; for (int q = 0; q < 8; ++q) { int tmp = wsum[q]; wsum[q] = run; run += tmp; } }
    __syncthreads();
    int r = g_bpre[b] + wsum[w] + (x - s);
    r += v0; if (base < n)     g_off[base + 1] = r;
    r += v1; if (base + 1 < n) g_off[base + 2] = r;
    r += v2; if (base + 2 < n) g_off[base + 3] = r;
    r += v3; if (base + 3 < n) g_off[base + 4] = r;
    if (b == 0 && t == 0) g_off[0] = 0;
}
__global__ void k_scatter(const int* __restrict__ ei, const int* __restrict__ et, int nE) {
    int e = blockIdx.x * blockDim.x + threadIdx.x;
    if (e >= nE) return;
    int d = ei[nE + e];
    int pos = g_off[d] + atomicAdd(&g_cursor[d], 1);
    g_csr[pos] = (ei[e] << 2) | (et[e] & 3);
}

// ---- HMMA typed encoder: 128 nodes of one type per block ----
__global__ void __launch_bounds__(256) k_encoder_mma(
    const int* __restrict__ z, const float* __restrict__ z_embed,
    const float* __restrict__ b1, const float* __restrict__ b2, int n)
{
    int t = blockIdx.y;
    int cntT = g_tcnt[t];
    int base = blockIdx.x * 128;
    if (base >= cntT) return;
    int cnt = min(128, cntT - base);

    extern __shared__ uint32_t sm[];
    uint32_t* Ah = sm;
    uint32_t* Al = Ah + 4608;
    uint32_t* Bh = Al + 4608;
    uint32_t* Bl = Bh + 4608;
    __shared__ int nds[128]; __shared__ int zz[128];
    __shared__ float lb1[128], lb2[128];

    int tid = threadIdx.x, lane = tid & 31, w = tid >> 5;
    if (tid < 128) {
        int m = tid;
        int node = (m < cnt) ? g_tlist[t * NMAX + base + m] : 0;
        nds[m] = node;
        zz[m] = z[node] * FEAT;
        lb1[m] = b1[t * 128 + m];
        lb2[m] = b2[t * 128 + m];
    }
    __syncthreads();

#pragma unroll
    for (int it = 0; it < 16; ++it) {
        int p = tid + it * 256;
        int m = p >> 5, kk = p & 31;
        float f0 = 0.f, f1 = 0.f;
        if (m < cnt) { int zr = zz[m]; f0 = z_embed[zr + 2 * kk]; f1 = z_embed[zr + 2 * kk + 1]; }
        uint32_t hw, lw; pkpair(f0, f1, hw, lw);
        Ah[m * ASTRIDE + kk] = hw; Al[m * ASTRIDE + kk] = lw;
    }
#pragma unroll
    for (int it = 0; it < 16; ++it) {
        int p = tid + it * 256;
        int j = p >> 5, kk = p & 31;
        uint2 v = *(const uint2*)&g_w1t[(t * 128 + j) * 64 + 2 * kk];
        Bh[j * ASTRIDE + kk] = (v.x & 0xffffu) | (v.y << 16);
        Bl[j * ASTRIDE + kk] = (v.x >> 16) | (v.y & 0xffff0000u);
    }
    __syncthreads();

    int r = w * 16 + (lane >> 2);
    int kq = lane & 3;
    float c[64];
#pragma unroll
    for (int i = 0; i < 64; ++i) c[i] = 0.f;

#pragma unroll
    for (int ks = 0; ks < 4; ++ks) {
        int kb = ks * 8;
        uint32_t ah[4], al[4];
        ah[0] = Ah[r * ASTRIDE + kb + kq];       ah[1] = Ah[(r + 8) * ASTRIDE + kb + kq];
        ah[2] = Ah[r * ASTRIDE + kb + 4 + kq];   ah[3] = Ah[(r + 8) * ASTRIDE + kb + 4 + kq];
        al[0] = Al[r * ASTRIDE + kb + kq];       al[1] = Al[(r + 8) * ASTRIDE + kb + kq];
        al[2] = Al[r * ASTRIDE + kb + 4 + kq];   al[3] = Al[(r + 8) * ASTRIDE + kb + 4 + kq];
#pragma unroll
        for (int nt = 0; nt < 16; ++nt) {
            int nj = nt * 8 + (lane >> 2);
            uint32_t bh[2], bl[2];
            bh[0] = Bh[nj * ASTRIDE + kb + kq]; bh[1] = Bh[nj * ASTRIDE + kb + 4 + kq];
            bl[0] = Bl[nj * ASTRIDE + kb + kq]; bl[1] = Bl[nj * ASTRIDE + kb + 4 + kq];
            mma16816(c + nt * 4, ah, bh);
            mma16816(c + nt * 4, ah, bl);
            mma16816(c + nt * 4, al, bh);
        }
    }

    uint32_t hA[32], lA[32];
#pragma unroll
    for (int nt = 0; nt < 16; ++nt) {
        int col = nt * 8 + 2 * kq;
        float y0 = fmaxf(c[nt * 4 + 0] + lb1[col], 0.f);
        float y1 = fmaxf(c[nt * 4 + 1] + lb1[col + 1], 0.f);
        float y2 = fmaxf(c[nt * 4 + 2] + lb1[col], 0.f);
        float y3 = fmaxf(c[nt * 4 + 3] + lb1[col + 1], 0.f);
        pkpair(y0, y1, hA[nt * 2], lA[nt * 2]);
        pkpair(y2, y3, hA[nt * 2 + 1], lA[nt * 2 + 1]);
    }

    float c2[64];
#pragma unroll
    for (int nt = 0; nt < 16; ++nt) {
        int col = nt * 8 + 2 * kq;
        c2[nt * 4 + 0] = lb2[col]; c2[nt * 4 + 1] = lb2[col + 1];
        c2[nt * 4 + 2] = lb2[col]; c2[nt * 4 + 3] = lb2[col + 1];
    }
#pragma unroll
    for (int ch = 0; ch < 2; ++ch) {
        __syncthreads();
#pragma unroll
        for (int it = 0; it < 16; ++it) {
            int p = tid + it * 256;
            int j = p >> 5, kk = p & 31;
            uint2 v = *(const uint2*)&g_w2t[(t * 128 + j) * 128 + ch * 64 + 2 * kk];
            Bh[j * ASTRIDE + kk] = (v.x & 0xffffu) | (v.y << 16);
            Bl[j * ASTRIDE + kk] = (v.x >> 16) | (v.y & 0xffff0000u);
        }
        __syncthreads();
#pragma unroll
        for (int ks = 0; ks < 4; ++ks) {
            int kb2 = ch * 4 + ks;
            uint32_t ah[4], al[4];
            ah[0] = hA[4 * kb2 + 0]; ah[1] = hA[4 * kb2 + 1];
            ah[2] = hA[4 * kb2 + 2]; ah[3] = hA[4 * kb2 + 3];
            al[0] = lA[4 * kb2 + 0]; al[1] = lA[4 * kb2 + 1];
            al[2] = lA[4 * kb2 + 2]; al[3] = lA[4 * kb2 + 3];
            int kb = ks * 8;
#pragma unroll
            for (int nt = 0; nt < 16; ++nt) {
                int nj = nt * 8 + (lane >> 2);
                uint32_t bh[2], bl[2];
                bh[0] = Bh[nj * ASTRIDE + kb + kq]; bh[1] = Bh[nj * ASTRIDE + kb + 4 + kq];
                bl[0] = Bl[nj * ASTRIDE + kb + kq]; bl[1] = Bl[nj * ASTRIDE + kb + 4 + kq];
                mma16816(c2 + nt * 4, ah, bh);
                mma16816(c2 + nt * 4, ah, bl);
                mma16816(c2 + nt * 4, al, bh);
            }
        }
    }

    int ma = r, mb = r + 8;
    int na = nds[ma], nb2 = nds[mb];
#pragma unroll
    for (int nt = 0; nt < 16; ++nt) {
        int col = nt * 8 + 2 * kq;
        int wi = nt * 4 + kq;
        if (ma < cnt) {
            float o0 = c2[nt * 4 + 0], o1 = c2[nt * 4 + 1];
            *(float2*)&g_xA[(size_t)na * HID + col] = make_float2(o0, o1);
            uint32_t hw, lw; pkpair(o0, o1, hw, lw);
            g_xhA[(size_t)na * 64 + wi] = hw; g_xlA[(size_t)na * 64 + wi] = lw;
        }
        if (mb < cnt) {
            float o2 = c2[nt * 4 + 2], o3 = c2[nt * 4 + 3];
            *(float2*)&g_xA[(size_t)nb2 * HID + col] = make_float2(o2, o3);
            uint32_t hw, lw; pkpair(o2, o3, hw, lw);
            g_xhB[0] = g_xhB[0];  // no-op placeholder removed below
            g_xhA[(size_t)nb2 * 64 + wi] = hw; g_xlA[(size_t)nb2 * 64 + wi] = lw;
        }
    }
}

// ---- aggregation (warp/node, unroll 8), emits bf16 plane pairs ----
__device__ __forceinline__ void acc4(float4& a, const float4& v) { a.x += v.x; a.y += v.y; a.z += v.z; a.w += v.w; }
__global__ void k_aggregate(int sel, int n) {
    int gw = (blockIdx.x * blockDim.x + threadIdx.x) >> 5;
    if (gw >= n) return;
    const float* __restrict__ x = sel ? g_xB : g_xA;
    int lane = threadIdx.x & 31;
    int s = g_off[gw], e = g_off[gw + 1];
    int deg = e - s;
    float inv = 1.f / (float)(deg >= 1 ? deg : 1);
    float4 a0 = make_float4(0, 0, 0, 0), a1 = a0, a2 = a0;
    int lo4 = lane * 4, i = s;
    for (; i + 8 <= e; i += 8) {
        int pp[8];
#pragma unroll
        for (int q = 0; q < 8; ++q) pp[q] = g_csr[i + q];
        float4 vv[8];
#pragma unroll
        for (int q = 0; q < 8; ++q) vv[q] = *(const float4*)(x + (size_t)(pp[q] >> 2) * HID + lo4);
#pragma unroll
        for (int q = 0; q < 8; ++q) {
            int et = pp[q] & 3;
            if (et == 0) acc4(a0, vv[q]); else if (et == 1) acc4(a1, vv[q]); else acc4(a2, vv[q]);
        }
    }
    for (; i < e; ++i) {
        int p = g_csr[i];
        float4 v = *(const float4*)(x + (size_t)(p >> 2) * HID + lo4);
        int et = p & 3; if (et == 0) acc4(a0, v); else if (et == 1) acc4(a1, v); else acc4(a2, v);
    }
    a0.x *= inv; a0.y *= inv; a0.z *= inv; a0.w *= inv;
    a1.x *= inv; a1.y *= inv; a1.z *= inv; a1.w *= inv;
    a2.x *= inv; a2.y *= inv; a2.z *= inv; a2.w *= inv;
    size_t ob = (size_t)gw * 192 + lane * 2;
    uint32_t h0, l0, h1, l1;
    pkpair(a0.x, a0.y, h0, l0); pkpair(a0.z, a0.w, h1, l1);
    *(uint2*)&g_aggh[ob] = make_uint2(h0, h1); *(uint2*)&g_aggl[ob] = make_uint2(l0, l1);
    pkpair(a1.x, a1.y, h0, l0); pkpair(a1.z, a1.w, h1, l1);
    *(uint2*)&g_aggh[ob + 64] = make_uint2(h0, h1); *(uint2*)&g_aggl[ob + 64] = make_uint2(l0, l1);
    pkpair(a2.x, a2.y, h0, l0); pkpair(a2.z, a2.w, h1, l1);
    *(uint2*)&g_aggh[ob + 128] = make_uint2(h0, h1); *(uint2*)&g_aggl[ob + 128] = make_uint2(l0, l1);
}

// ---- HMMA GEMM with cp.async double-buffered staging + fused LN (+pool on layer 1) ----
__global__ void __launch_bounds__(256) k_gemm_mma(
    int layer, const float* __restrict__ lin_b_all,
    const float* __restrict__ ln_g_all, const float* __restrict__ ln_b_all, int n)
{
    extern __shared__ uint32_t sm[];      // 2 stages x 4 planes x 4608 u32
    __shared__ float lb[128], lgg[128], lbb[128], psum[128];

    int tid = threadIdx.x, lane = tid & 31, w = tid >> 5;
    int base = blockIdx.x * 128;
    if (tid < 128) {
        lb[tid]  = lin_b_all[layer * 128 + tid];
        lgg[tid] = ln_g_all[layer * 128 + tid];
        lbb[tid] = ln_b_all[layer * 128 + tid];
        psum[tid] = 0.f;
    }
    const uint32_t* xh = layer ? g_xhB : g_xhA;
    const uint32_t* xl = layer ? g_xlB : g_xlA;
    uint32_t smu = smem_u32(sm);

    // stage issue: ch in [0,8), stage buffer sidx in {0,1}
    auto issue = [&](int ch, int sidx) {
        uint32_t sb = smu + sidx * 73728;
#pragma unroll
        for (int it = 0; it < 4; ++it) {
            int p = tid + it * 256;
            int m = p >> 3, q = p & 7;
            int node = base + m;
            int cn = node < n ? node : 0;
            int zf = (node < n) ? 16 : 0;
            const uint32_t* sh;
            const uint32_t* sl;
            if (ch < 2) { size_t wv = (size_t)cn * 64 + ch * 32 + q * 4; sh = &xh[wv]; sl = &xl[wv]; }
            else { size_t wv = (size_t)cn * 192 + (ch - 2) * 32 + q * 4; sh = &g_aggh[wv]; sl = &g_aggl[wv]; }
            uint32_t d = sb + (m * ASTRIDE + q * 4) * 4;
            cpa16(d, sh, zf);
            cpa16(d + 18432, sl, zf);
        }
#pragma unroll
        for (int it = 0; it < 4; ++it) {
            int p = tid + it * 256;
            int j = p >> 3, q = p & 7;
            size_t wv = (size_t)(layer * 128 + j) * 256 + ch * 32 + q * 4;
            uint32_t d = sb + (j * ASTRIDE + q * 4) * 4;
            cpa16(d + 36864, &g_wth[wv], 16);
            cpa16(d + 55296, &g_wtl[wv], 16);
        }
        CPA_COMMIT();
    };

    float c[64];
#pragma unroll
    for (int i = 0; i < 64; ++i) c[i] = 0.f;
    int r = w * 16 + (lane >> 2);
    int kq = lane & 3;

    issue(0, 0);
    for (int ch = 0; ch < 8; ++ch) {
        __syncthreads();
        if (ch + 1 < 8) issue(ch + 1, (ch + 1) & 1);
        if (ch + 1 < 8) { CPA_WAIT1(); } else { CPA_WAIT0(); }
        __syncthreads();
        uint32_t* Ah = sm + (ch & 1) * 18432;
        uint32_t* Al = Ah + 4608;
        uint32_t* Bh = Al + 4608;
        uint32_t* Bl = Bh + 4608;
#pragma unroll
        for (int ks = 0; ks < 4; ++ks) {
            int kb = ks * 8;
            uint32_t ah[4], al[4];
            ah[0] = Ah[r * ASTRIDE + kb + kq];     ah[1] = Ah[(r + 8) * ASTRIDE + kb + kq];
            ah[2] = Ah[r * ASTRIDE + kb + 4 + kq]; ah[3] = Ah[(r + 8) * ASTRIDE + kb + 4 + kq];
            al[0] = Al[r * ASTRIDE + kb + kq];     al[1] = Al[(r + 8) * ASTRIDE + kb + kq];
            al[2] = Al[r * ASTRIDE + kb + 4 + kq]; al[3] = Al[(r + 8) * ASTRIDE + kb + 4 + kq];
#pragma unroll
            for (int nt = 0; nt < 16; ++nt) {
                int nj = nt * 8 + (lane >> 2);
                uint32_t bh[2], bl[2];
                bh[0] = Bh[nj * ASTRIDE + kb + kq]; bh[1] = Bh[nj * ASTRIDE + kb + 4 + kq];
                bl[0] = Bl[nj * ASTRIDE + kb + kq]; bl[1] = Bl[nj * ASTRIDE + kb + 4 + kq];
                mma16816(c + nt * 4, ah, bh);
                mma16816(c + nt * 4, ah, bl);
                mma16816(c + nt * 4, al, bh);
            }
        }
    }

    float s1a = 0.f, s2a = 0.f, s1b = 0.f, s2b = 0.f;
#pragma unroll
    for (int nt = 0; nt < 16; ++nt) {
        int col = nt * 8 + 2 * kq;
        float y0 = c[nt * 4 + 0] + lb[col], y1 = c[nt * 4 + 1] + lb[col + 1];
        float y2 = c[nt * 4 + 2] + lb[col], y3 = c[nt * 4 + 3] + lb[col + 1];
        c[nt * 4 + 0] = y0; c[nt * 4 + 1] = y1; c[nt * 4 + 2] = y2; c[nt * 4 + 3] = y3;
        s1a += y0 + y1; s2a += y0 * y0 + y1 * y1;
        s1b += y2 + y3; s2b += y2 * y2 + y3 * y3;
    }
#pragma unroll
    for (int o = 1; o <= 2; o <<= 1) {
        s1a += __shfl_xor_sync(0xffffffffu, s1a, o);
        s2a += __shfl_xor_sync(0xffffffffu, s2a, o);
        s1b += __shfl_xor_sync(0xffffffffu, s1b, o);
        s2b += __shfl_xor_sync(0xffffffffu, s2b, o);
    }
    float mua = s1a * (1.f / 128.f), mub = s1b * (1.f / 128.f);
    float rsa = rsqrtf(s2a * (1.f / 128.f) - mua * mua + 1e-5f);
    float rsb = rsqrtf(s2b * (1.f / 128.f) - mub * mub + 1e-5f);

    float* xout = layer ? g_xA : g_xB;
    uint32_t* xouth = layer ? g_xhA : g_xhB;
    uint32_t* xoutl = layer ? g_xlA : g_xlB;
    int na = base + r, nbd = na + 8;
#pragma unroll
    for (int nt = 0; nt < 16; ++nt) {
        int col = nt * 8 + 2 * kq;
        int wi = nt * 4 + kq;
        float gg0 = lgg[col], gg1 = lgg[col + 1], bb0 = lbb[col], bb1 = lbb[col + 1];
        float o0 = (c[nt * 4 + 0] - mua) * rsa * gg0 + bb0;
        float o1 = (c[nt * 4 + 1] - mua) * rsa * gg1 + bb1;
        float o2 = (c[nt * 4 + 2] - mub) * rsb * gg0 + bb0;
        float o3 = (c[nt * 4 + 3] - mub) * rsb * gg1 + bb1;
        if (na < n) {
            *(float2*)&xout[(size_t)na * HID + col] = make_float2(o0, o1);
            uint32_t hw, lw; pkpair(o0, o1, hw, lw);
            xouth[(size_t)na * 64 + wi] = hw; xoutl[(size_t)na * 64 + wi] = lw;
        }
        if (nbd < n) {
            *(float2*)&xout[(size_t)nbd * HID + col] = make_float2(o2, o3);
            uint32_t hw, lw; pkpair(o2, o3, hw, lw);
            xouth[(size_t)nbd * 64 + wi] = hw; xoutl[(size_t)nbd * 64 + wi] = lw;
        }
        if (layer == 1) {
            float v0 = (na < n ? o0 : 0.f) + (nbd < n ? o2 : 0.f);
            float v1 = (na < n ? o1 : 0.f) + (nbd < n ? o3 : 0.f);
#pragma unroll
            for (int off = 4; off <= 16; off <<= 1) {
                v0 += __shfl_xor_sync(0xffffffffu, v0, off);
                v1 += __shfl_xor_sync(0xffffffffu, v1, off);
            }
            if (lane < 4) { atomicAdd(&psum[col], v0); atomicAdd(&psum[col + 1], v1); }
        }
    }
    if (layer == 1) {
        __syncthreads();
        if (tid < 128) atomicAdd(&g_pooled[tid], psum[tid]);
    }
}

// ---- head ----
__global__ void k_final(const float* __restrict__ reg_w, const float* __restrict__ reg_b,
                        float* __restrict__ out, int n) {
    int tid = threadIdx.x;
    float v = g_pooled[tid] * (1.f / (float)n) * reg_w[tid];
#pragma unroll
    for (int o = 16; o; o >>= 1) v += __shfl_xor_sync(0xffffffffu, v, o);
    __shared__ float r[4];
    if ((tid & 31) == 0) r[tid >> 5] = v;
    __syncthreads();
    if (tid == 0) out[0] = r[0] + r[1] + r[2] + r[3] + reg_b[0];
}

extern "C" void kernel_launch(void* const* d_in, const int* in_sizes, int n_in,
                              void* d_out, int out_size) {
    const int*   z          = (const int*)d_in[0];
    const int*   node_type  = (const int*)d_in[1];
    const int*   edge_index = (const int*)d_in[2];
    const int*   edge_type  = (const int*)d_in[3];
    const float* z_embed    = (const float*)d_in[4];
    const float* enc_w1     = (const float*)d_in[5];
    const float* enc_b1     = (const float*)d_in[6];
    const float* enc_w2     = (const float*)d_in[7];
    const float* enc_b2     = (const float*)d_in[8];
    const float* lin_w      = (const float*)d_in[9];
    const float* lin_b      = (const float*)d_in[10];
    const float* rel_w      = (const float*)d_in[11];
    const float* ln_g       = (const float*)d_in[12];
    const float* ln_b       = (const float*)d_in[13];
    const float* reg_w      = (const float*)d_in[14];
    const float* reg_b      = (const float*)d_in[15];
    float* out = (float*)d_out;

    int n = in_sizes[0];
    int E = in_sizes[3];
    int nb = (n + 1023) / 1024;
    const int ESM = 73728;       // encoder single-stage smem
    const int GSM = 147456;      // gemm double-buffered smem
    cudaFuncSetAttribute(k_gemm_mma, cudaFuncAttributeMaxDynamicSharedMemorySize, GSM);
    cudaFuncSetAttribute(k_encoder_mma, cudaFuncAttributeMaxDynamicSharedMemorySize, ESM);

    k_init<<<(n + 255) / 256, 256>>>(n);
    k_setup<<<(E + 255) / 256, 256>>>(node_type, edge_index, lin_w, rel_w, enc_w1, enc_w2, n, E);
    k_scan1<<<nb, 256>>>(n);
    dim3 egrid((n + 127) / 128, 4);
    k_encoder_mma<<<egrid, 256, ESM>>>(z, z_embed, enc_b1, enc_b2, n);   // 4th launch (profiled)
    k_scan2<<<1, 32>>>(nb);
    k_scan3<<<nb, 256>>>(n);
    k_scatter<<<(E + 255) / 256, 256>>>(edge_index, edge_type, E);

    int agrid = (n * 32 + 255) / 256;
    int ggrid = (n + 127) / 128;
    k_aggregate<<<agrid, 256>>>(0, n);
    k_gemm_mma<<<ggrid, 256, GSM>>>(0, lin_b, ln_g, ln_b, n);
    k_aggregate<<<agrid, 256>>>(1, n);
    k_gemm_mma<<<ggrid, 256, GSM>>>(1, lin_b, ln_g, ln_b, n);

    k_final<<<1, 128>>>(reg_w, reg_b, out, n);
}

// round 8
// speedup vs baseline: 2.4426x; 1.0337x over previous
#include <cuda_runtime.h>
#include <cuda_bf16.h>
#include <stdint.h>

#define NMAX 50000
#define EMAX 800000
#define HID 128
#define FEAT 64
#define ASTRIDE 36   // u32 words per 64-k row (144B) -> conflict-free fragment LDS
#define HSTRIDE 68   // u32 words per 128-k row (encoder h planes), 68%32==4 -> conflict-free

__device__ float g_xA[(size_t)NMAX * HID];
__device__ float g_xB[(size_t)NMAX * HID];
// bf16 plane arrays: word i = pair of k (2*i, 2*i+1)
__device__ uint32_t g_xhA[(size_t)NMAX * 64];
__device__ uint32_t g_xlA[(size_t)NMAX * 64];
__device__ uint32_t g_xhB[(size_t)NMAX * 64];
__device__ uint32_t g_xlB[(size_t)NMAX * 64];
__device__ uint32_t g_aggh[(size_t)NMAX * 192];
__device__ uint32_t g_aggl[(size_t)NMAX * 192];
__device__ uint32_t g_wth[2 * 128 * 256];        // [l][j][kpair]
__device__ uint32_t g_wtl[2 * 128 * 256];
__device__ uint32_t g_w1t[4 * 128 * 64];         // encoder packed hi|lo<<16
__device__ uint32_t g_w2t[4 * 128 * 128];
__device__ int   g_counts[NMAX];
__device__ int   g_off[NMAX + 1];
__device__ int   g_cursor[NMAX];
__device__ int   g_csr[EMAX];
__device__ int   g_tcnt[4];
__device__ int   g_tlist[4 * NMAX];
__device__ float g_pooled[HID];
__device__ int   g_bsum[64];
__device__ int   g_bpre[64];
__device__ int   g_scanctr;

__device__ __forceinline__ uint32_t pkbf(float v) {
    __nv_bfloat16 h = __float2bfloat16(v);
    __nv_bfloat16 l = __float2bfloat16(v - __bfloat162float(h));
    return (uint32_t)__bfloat16_as_ushort(h) | ((uint32_t)__bfloat16_as_ushort(l) << 16);
}
__device__ __forceinline__ void pkpair(float f0, float f1, uint32_t& hw, uint32_t& lw) {
    __nv_bfloat162 h2 = __floats2bfloat162_rn(f0, f1);
    hw = *(uint32_t*)&h2;
    float r0 = f0 - __bfloat162float(h2.x);
    float r1 = f1 - __bfloat162float(h2.y);
    __nv_bfloat162 l2 = __floats2bfloat162_rn(r0, r1);
    lw = *(uint32_t*)&l2;
}
__device__ __forceinline__ void mma16816(float* c, const uint32_t* a, const uint32_t* b) {
    asm volatile(
        "mma.sync.aligned.m16n8k16.row.col.f32.bf16.bf16.f32 "
        "{%0,%1,%2,%3}, {%4,%5,%6,%7}, {%8,%9}, {%0,%1,%2,%3};"
        : "+f"(c[0]), "+f"(c[1]), "+f"(c[2]), "+f"(c[3])
        : "r"(a[0]), "r"(a[1]), "r"(a[2]), "r"(a[3]), "r"(b[0]), "r"(b[1]));
}
__device__ __forceinline__ uint32_t smem_u32(const void* p) {
    uint32_t a; asm("{ .reg .u64 t; cvta.to.shared.u64 t, %1; cvt.u32.u64 %0, t; }" : "=r"(a) : "l"(p)); return a;
}
__device__ __forceinline__ void cpa16(uint32_t dst, const void* src, int srcsz) {
    asm volatile("cp.async.cg.shared.global [%0], [%1], 16, %2;" :: "r"(dst), "l"(src), "r"(srcsz) : "memory");
}
#define CPA_COMMIT() asm volatile("cp.async.commit_group;" ::: "memory")
#define CPA_WAIT1() asm volatile("cp.async.wait_group 1;" ::: "memory")
#define CPA_WAIT0() asm volatile("cp.async.wait_group 0;" ::: "memory")

// ---- init ----
__global__ void k_init(int n) {
    int i = blockIdx.x * blockDim.x + threadIdx.x;
    if (i < n) { g_counts[i] = 0; g_cursor[i] = 0; }
    if (i < HID) g_pooled[i] = 0.f;
    if (i < 4) g_tcnt[i] = 0;
    if (i == 4) g_scanctr = 0;
}

// ---- fused setup: bucket + count_deg + prep_w + prep_enc ----
__global__ void __launch_bounds__(256) k_setup(
    const int* __restrict__ nt, const int* __restrict__ ei,
    const float* __restrict__ lin_w, const float* __restrict__ rel_w,
    const float* __restrict__ w1, const float* __restrict__ w2, int n, int E)
{
    __shared__ int cnt[4]; __shared__ int basei[4]; __shared__ unsigned cur[4];
    int t = threadIdx.x;
    int gid = blockIdx.x * 256 + t;
    if (t < 4) { cnt[t] = 0; cur[t] = 0; }
    __syncthreads();
    int ty = (gid < n) ? nt[gid] : -1;
    if (ty >= 0) atomicAdd(&cnt[ty], 1);
    __syncthreads();
    if (t < 4) basei[t] = atomicAdd(&g_tcnt[t], cnt[t]);
    __syncthreads();
    if (ty >= 0) { int pos = atomicAdd(&cur[ty], 1u); g_tlist[ty * NMAX + basei[ty] + pos] = gid; }
    if (gid < E) atomicAdd(&g_counts[ei[E + gid]], 1);
    if (gid < 65536) {
        int l = gid >> 15, rem = gid & 32767, j = rem >> 8, kp = rem & 255;
        int kg = 2 * kp;
        float w0, w1v;
        if (kg < 128) { w0 = lin_w[l * 16384 + kg * 128 + j]; w1v = lin_w[l * 16384 + (kg + 1) * 128 + j]; }
        else { w0 = rel_w[l * 49152 + (kg - 128) * 128 + j]; w1v = rel_w[l * 49152 + (kg - 127) * 128 + j]; }
        uint32_t hw, lw; pkpair(w0, w1v, hw, lw);
        g_wth[gid] = hw; g_wtl[gid] = lw;
    }
    if (gid < 32768) {
        int tt = gid >> 13, rem = gid & 8191, j = rem >> 6, d = rem & 63;
        g_w1t[gid] = pkbf(w1[tt * 8192 + d * 128 + j]);
    } else if (gid < 98304) {
        int i2 = gid - 32768;
        int tt = i2 >> 14, rem = i2 & 16383, j = rem >> 7, k = rem & 127;
        g_w2t[i2] = pkbf(w2[tt * 16384 + k * 128 + j]);
    }
}

// ---- scan phase 1+2 fused (last-block does the block-sum scan) ----
__global__ void __launch_bounds__(256) k_scan12(int n, int nb) {
    int b = blockIdx.x, t = threadIdx.x;
    int base = b * 1024 + t * 4;
    int s = 0;
    if (base + 3 < n) { int4 c = *(const int4*)&g_counts[base]; s = c.x + c.y + c.z + c.w; }
    else for (int q = 0; q < 4; ++q) if (base + q < n) s += g_counts[base + q];
#pragma unroll
    for (int o = 16; o; o >>= 1) s += __shfl_xor_sync(0xffffffffu, s, o);
    __shared__ int ws[8];
    __shared__ int amlast;
    if ((t & 31) == 0) ws[t >> 5] = s;
    __syncthreads();
    if (t == 0) {
        int tot = 0;
#pragma unroll
        for (int w = 0; w < 8; ++w) tot += ws[w];
        g_bsum[b] = tot;
        __threadfence();
        amlast = (atomicAdd(&g_scanctr, 1) == nb - 1);
    }
    __syncthreads();
    if (amlast && t < 32) {
        int lane = t; int carry = 0;
        for (int bb = 0; bb < nb; bb += 32) {
            int i = bb + lane;
            int v = (i < nb) ? g_bsum[i] : 0, x = v;
#pragma unroll
            for (int d = 1; d < 32; d <<= 1) { int u = __shfl_up_sync(0xffffffffu, x, d); if (lane >= d) x += u; }
            if (i < nb) g_bpre[i] = carry + x - v;
            carry += __shfl_sync(0xffffffffu, x, 31);
        }
    }
}
__global__ void __launch_bounds__(256) k_scan3(int n) {
    __shared__ int wsum[8];
    int b = blockIdx.x, t = threadIdx.x, lane = t & 31, w = t >> 5;
    int base = b * 1024 + t * 4;
    int v0 = 0, v1 = 0, v2 = 0, v3 = 0;
    if (base + 3 < n) { int4 c = *(const int4*)&g_counts[base]; v0 = c.x; v1 = c.y; v2 = c.z; v3 = c.w; }
    else { if (base < n) v0 = g_counts[base]; if (base + 1 < n) v1 = g_counts[base + 1];
           if (base + 2 < n) v2 = g_counts[base + 2]; if (base + 3 < n) v3 = g_counts[base + 3]; }
    int s = v0 + v1 + v2 + v3, x = s;
#pragma unroll
    for (int d = 1; d < 32; d <<= 1) { int u = __shfl_up_sync(0xffffffffu, x, d); if (lane >= d) x += u; }
    if (lane == 31) wsum[w] = x;
    __syncthreads();
    if (t == 0) { int run = 0; for (int q = 0; q < 8; ++q) { int tmp = wsum[q]; wsum[q] = run; run += tmp; } }
    __syncthreads();
    int r = g_bpre[b] + wsum[w] + (x - s);
    r += v0; if (base < n)     g_off[base + 1] = r;
    r += v1; if (base + 1 < n) g_off[base + 2] = r;
    r += v2; if (base + 2 < n) g_off[base + 3] = r;
    r += v3; if (base + 3 < n) g_off[base + 4] = r;
    if (b == 0 && t == 0) g_off[0] = 0;
}
__global__ void k_scatter(const int* __restrict__ ei, const int* __restrict__ et, int nE) {
    int e = blockIdx.x * blockDim.x + threadIdx.x;
    if (e >= nE) return;
    int d = ei[nE + e];
    int pos = g_off[d] + atomicAdd(&g_cursor[d], 1);
    g_csr[pos] = (ei[e] << 2) | (et[e] & 3);
}

// ---- HMMA typed encoder: 128 nodes of one type per block; h routed via smem ----
__global__ void __launch_bounds__(256, 2) k_encoder_mma(
    const int* __restrict__ z, const float* __restrict__ z_embed,
    const float* __restrict__ b1, const float* __restrict__ b2, int n)
{
    int t = blockIdx.y;
    int cntT = g_tcnt[t];
    int base = blockIdx.x * 128;
    if (base >= cntT) return;
    int cnt = min(128, cntT - base);

    extern __shared__ uint32_t sm[];
    uint32_t* Hh = sm;                 // 128*HSTRIDE (stage1: embeddings words 0..31; stage2: h words 0..63)
    uint32_t* Hl = Hh + 128 * HSTRIDE;
    uint32_t* Bh = Hl + 128 * HSTRIDE; // 128*ASTRIDE
    uint32_t* Bl = Bh + 128 * ASTRIDE;
    __shared__ int nds[128]; __shared__ int zz[128];
    __shared__ float lb1[128], lb2[128];

    int tid = threadIdx.x, lane = tid & 31, w = tid >> 5;
    if (tid < 128) {
        int m = tid;
        int node = (m < cnt) ? g_tlist[t * NMAX + base + m] : 0;
        nds[m] = node;
        zz[m] = z[node] * FEAT;
        lb1[m] = b1[t * 128 + m];
        lb2[m] = b2[t * 128 + m];
    }
    __syncthreads();

    // stage-1 A: embeddings [128 x 64] into H planes (words 0..31)
#pragma unroll
    for (int it = 0; it < 16; ++it) {
        int p = tid + it * 256;
        int m = p >> 5, kk = p & 31;
        float f0 = 0.f, f1 = 0.f;
        if (m < cnt) { int zr = zz[m]; f0 = z_embed[zr + 2 * kk]; f1 = z_embed[zr + 2 * kk + 1]; }
        uint32_t hw, lw; pkpair(f0, f1, hw, lw);
        Hh[m * HSTRIDE + kk] = hw; Hl[m * HSTRIDE + kk] = lw;
    }
#pragma unroll
    for (int it = 0; it < 16; ++it) {
        int p = tid + it * 256;
        int j = p >> 5, kk = p & 31;
        uint2 v = *(const uint2*)&g_w1t[(t * 128 + j) * 64 + 2 * kk];
        Bh[j * ASTRIDE + kk] = (v.x & 0xffffu) | (v.y << 16);
        Bl[j * ASTRIDE + kk] = (v.x >> 16) | (v.y & 0xffff0000u);
    }
    __syncthreads();

    int r = w * 16 + (lane >> 2);
    int kq = lane & 3;
    {
        float c[64];
#pragma unroll
        for (int i = 0; i < 64; ++i) c[i] = 0.f;
#pragma unroll
        for (int ks = 0; ks < 4; ++ks) {
            int kb = ks * 8;
            uint32_t ah[4], al[4];
            ah[0] = Hh[r * HSTRIDE + kb + kq];       ah[1] = Hh[(r + 8) * HSTRIDE + kb + kq];
            ah[2] = Hh[r * HSTRIDE + kb + 4 + kq];   ah[3] = Hh[(r + 8) * HSTRIDE + kb + 4 + kq];
            al[0] = Hl[r * HSTRIDE + kb + kq];       al[1] = Hl[(r + 8) * HSTRIDE + kb + kq];
            al[2] = Hl[r * HSTRIDE + kb + 4 + kq];   al[3] = Hl[(r + 8) * HSTRIDE + kb + 4 + kq];
#pragma unroll
            for (int nt = 0; nt < 16; ++nt) {
                int nj = nt * 8 + (lane >> 2);
                uint32_t bh[2], bl[2];
                bh[0] = Bh[nj * ASTRIDE + kb + kq]; bh[1] = Bh[nj * ASTRIDE + kb + 4 + kq];
                bl[0] = Bl[nj * ASTRIDE + kb + kq]; bl[1] = Bl[nj * ASTRIDE + kb + 4 + kq];
                mma16816(c + nt * 4, ah, bh);
                mma16816(c + nt * 4, ah, bl);
                mma16816(c + nt * 4, al, bh);
            }
        }
        __syncthreads();   // all stage-1 reads done before overwriting H with h
        // bias + relu, pack h into H planes (word = 4nt+kq, rows r and r+8)
#pragma unroll
        for (int nt = 0; nt < 16; ++nt) {
            int col = nt * 8 + 2 * kq;
            float y0 = fmaxf(c[nt * 4 + 0] + lb1[col], 0.f);
            float y1 = fmaxf(c[nt * 4 + 1] + lb1[col + 1], 0.f);
            float y2 = fmaxf(c[nt * 4 + 2] + lb1[col], 0.f);
            float y3 = fmaxf(c[nt * 4 + 3] + lb1[col + 1], 0.f);
            uint32_t hw, lw;
            pkpair(y0, y1, hw, lw);
            Hh[r * HSTRIDE + 4 * nt + kq] = hw; Hl[r * HSTRIDE + 4 * nt + kq] = lw;
            pkpair(y2, y3, hw, lw);
            Hh[(r + 8) * HSTRIDE + 4 * nt + kq] = hw; Hl[(r + 8) * HSTRIDE + 4 * nt + kq] = lw;
        }
    }

    float c2[64];
#pragma unroll
    for (int nt = 0; nt < 16; ++nt) {
        int col = nt * 8 + 2 * kq;
        c2[nt * 4 + 0] = lb2[col]; c2[nt * 4 + 1] = lb2[col + 1];
        c2[nt * 4 + 2] = lb2[col]; c2[nt * 4 + 3] = lb2[col + 1];
    }
#pragma unroll
    for (int ch = 0; ch < 2; ++ch) {
        __syncthreads();
#pragma unroll
        for (int it = 0; it < 16; ++it) {
            int p = tid + it * 256;
            int j = p >> 5, kk = p & 31;
            uint2 v = *(const uint2*)&g_w2t[(t * 128 + j) * 128 + ch * 64 + 2 * kk];
            Bh[j * ASTRIDE + kk] = (v.x & 0xffffu) | (v.y << 16);
            Bl[j * ASTRIDE + kk] = (v.x >> 16) | (v.y & 0xffff0000u);
        }
        __syncthreads();
#pragma unroll
        for (int ks = 0; ks < 4; ++ks) {
            int kw = (ch * 4 + ks) * 8;   // h word base for this k-tile
            uint32_t ah[4], al[4];
            ah[0] = Hh[r * HSTRIDE + kw + kq];       ah[1] = Hh[(r + 8) * HSTRIDE + kw + kq];
            ah[2] = Hh[r * HSTRIDE + kw + 4 + kq];   ah[3] = Hh[(r + 8) * HSTRIDE + kw + 4 + kq];
            al[0] = Hl[r * HSTRIDE + kw + kq];       al[1] = Hl[(r + 8) * HSTRIDE + kw + kq];
            al[2] = Hl[r * HSTRIDE + kw + 4 + kq];   al[3] = Hl[(r + 8) * HSTRIDE + kw + 4 + kq];
            int kb = ks * 8;
#pragma unroll
            for (int nt = 0; nt < 16; ++nt) {
                int nj = nt * 8 + (lane >> 2);
                uint32_t bh[2], bl[2];
                bh[0] = Bh[nj * ASTRIDE + kb + kq]; bh[1] = Bh[nj * ASTRIDE + kb + 4 + kq];
                bl[0] = Bl[nj * ASTRIDE + kb + kq]; bl[1] = Bl[nj * ASTRIDE + kb + 4 + kq];
                mma16816(c2 + nt * 4, ah, bh);
                mma16816(c2 + nt * 4, ah, bl);
                mma16816(c2 + nt * 4, al, bh);
            }
        }
    }

    int ma = r, mb = r + 8;
    int na = nds[ma], nb2 = nds[mb];
#pragma unroll
    for (int nt = 0; nt < 16; ++nt) {
        int col = nt * 8 + 2 * kq;
        int wi = nt * 4 + kq;
        if (ma < cnt) {
            float o0 = c2[nt * 4 + 0], o1 = c2[nt * 4 + 1];
            *(float2*)&g_xA[(size_t)na * HID + col] = make_float2(o0, o1);
            uint32_t hw, lw; pkpair(o0, o1, hw, lw);
            g_xhA[(size_t)na * 64 + wi] = hw; g_xlA[(size_t)na * 64 + wi] = lw;
        }
        if (mb < cnt) {
            float o2 = c2[nt * 4 + 2], o3 = c2[nt * 4 + 3];
            *(float2*)&g_xA[(size_t)nb2 * HID + col] = make_float2(o2, o3);
            uint32_t hw, lw; pkpair(o2, o3, hw, lw);
            g_xhA[(size_t)nb2 * 64 + wi] = hw; g_xlA[(size_t)nb2 * 64 + wi] = lw;
        }
    }
}

// ---- aggregation (warp/node, tiers 8/4/1), emits bf16 plane pairs ----
__device__ __forceinline__ void acc4(float4& a, const float4& v) { a.x += v.x; a.y += v.y; a.z += v.z; a.w += v.w; }
__global__ void k_aggregate(int sel, int n) {
    int gw = (blockIdx.x * blockDim.x + threadIdx.x) >> 5;
    if (gw >= n) return;
    const float* __restrict__ x = sel ? g_xB : g_xA;
    int lane = threadIdx.x & 31;
    int s = g_off[gw], e = g_off[gw + 1];
    int deg = e - s;
    float inv = 1.f / (float)(deg >= 1 ? deg : 1);
    float4 a0 = make_float4(0, 0, 0, 0), a1 = a0, a2 = a0;
    int lo4 = lane * 4, i = s;
    for (; i + 8 <= e; i += 8) {
        int pp[8];
#pragma unroll
        for (int q = 0; q < 8; ++q) pp[q] = g_csr[i + q];
        float4 vv[8];
#pragma unroll
        for (int q = 0; q < 8; ++q) vv[q] = *(const float4*)(x + (size_t)(pp[q] >> 2) * HID + lo4);
#pragma unroll
        for (int q = 0; q < 8; ++q) {
            int et = pp[q] & 3;
            if (et == 0) acc4(a0, vv[q]); else if (et == 1) acc4(a1, vv[q]); else acc4(a2, vv[q]);
        }
    }
    if (i + 4 <= e) {
        int pp[4];
#pragma unroll
        for (int q = 0; q < 4; ++q) pp[q] = g_csr[i + q];
        float4 vv[4];
#pragma unroll
        for (int q = 0; q < 4; ++q) vv[q] = *(const float4*)(x + (size_t)(pp[q] >> 2) * HID + lo4);
#pragma unroll
        for (int q = 0; q < 4; ++q) {
            int et = pp[q] & 3;
            if (et == 0) acc4(a0, vv[q]); else if (et == 1) acc4(a1, vv[q]); else acc4(a2, vv[q]);
        }
        i += 4;
    }
    for (; i < e; ++i) {
        int p = g_csr[i];
        float4 v = *(const float4*)(x + (size_t)(p >> 2) * HID + lo4);
        int et = p & 3; if (et == 0) acc4(a0, v); else if (et == 1) acc4(a1, v); else acc4(a2, v);
    }
    a0.x *= inv; a0.y *= inv; a0.z *= inv; a0.w *= inv;
    a1.x *= inv; a1.y *= inv; a1.z *= inv; a1.w *= inv;
    a2.x *= inv; a2.y *= inv; a2.z *= inv; a2.w *= inv;
    size_t ob = (size_t)gw * 192 + lane * 2;
    uint32_t h0, l0, h1, l1;
    pkpair(a0.x, a0.y, h0, l0); pkpair(a0.z, a0.w, h1, l1);
    *(uint2*)&g_aggh[ob] = make_uint2(h0, h1); *(uint2*)&g_aggl[ob] = make_uint2(l0, l1);
    pkpair(a1.x, a1.y, h0, l0); pkpair(a1.z, a1.w, h1, l1);
    *(uint2*)&g_aggh[ob + 64] = make_uint2(h0, h1); *(uint2*)&g_aggl[ob + 64] = make_uint2(l0, l1);
    pkpair(a2.x, a2.y, h0, l0); pkpair(a2.z, a2.w, h1, l1);
    *(uint2*)&g_aggh[ob + 128] = make_uint2(h0, h1); *(uint2*)&g_aggl[ob + 128] = make_uint2(l0, l1);
}

// ---- HMMA GEMM with cp.async double-buffered staging + fused LN (+pool on layer 1) ----
__global__ void __launch_bounds__(256) k_gemm_mma(
    int layer, const float* __restrict__ lin_b_all,
    const float* __restrict__ ln_g_all, const float* __restrict__ ln_b_all, int n)
{
    extern __shared__ uint32_t sm[];
    __shared__ float lb[128], lgg[128], lbb[128], psum[128];

    int tid = threadIdx.x, lane = tid & 31, w = tid >> 5;
    int base = blockIdx.x * 128;
    if (tid < 128) {
        lb[tid]  = lin_b_all[layer * 128 + tid];
        lgg[tid] = ln_g_all[layer * 128 + tid];
        lbb[tid] = ln_b_all[layer * 128 + tid];
        psum[tid] = 0.f;
    }
    const uint32_t* xh = layer ? g_xhB : g_xhA;
    const uint32_t* xl = layer ? g_xlB : g_xlA;
    uint32_t smu = smem_u32(sm);

    auto issue = [&](int ch, int sidx) {
        uint32_t sb = smu + sidx * 73728;
#pragma unroll
        for (int it = 0; it < 4; ++it) {
            int p = tid + it * 256;
            int m = p >> 3, q = p & 7;
            int node = base + m;
            int cn = node < n ? node : 0;
            int zf = (node < n) ? 16 : 0;
            const uint32_t* sh;
            const uint32_t* sl;
            if (ch < 2) { size_t wv = (size_t)cn * 64 + ch * 32 + q * 4; sh = &xh[wv]; sl = &xl[wv]; }
            else { size_t wv = (size_t)cn * 192 + (ch - 2) * 32 + q * 4; sh = &g_aggh[wv]; sl = &g_aggl[wv]; }
            uint32_t d = sb + (m * ASTRIDE + q * 4) * 4;
            cpa16(d, sh, zf);
            cpa16(d + 18432, sl, zf);
        }
#pragma unroll
        for (int it = 0; it < 4; ++it) {
            int p = tid + it * 256;
            int j = p >> 3, q = p & 7;
            size_t wv = (size_t)(layer * 128 + j) * 256 + ch * 32 + q * 4;
            uint32_t d = sb + (j * ASTRIDE + q * 4) * 4;
            cpa16(d + 36864, &g_wth[wv], 16);
            cpa16(d + 55296, &g_wtl[wv], 16);
        }
        CPA_COMMIT();
    };

    float c[64];
#pragma unroll
    for (int i = 0; i < 64; ++i) c[i] = 0.f;
    int r = w * 16 + (lane >> 2);
    int kq = lane & 3;

    issue(0, 0);
    for (int ch = 0; ch < 8; ++ch) {
        __syncthreads();
        if (ch + 1 < 8) issue(ch + 1, (ch + 1) & 1);
        if (ch + 1 < 8) { CPA_WAIT1(); } else { CPA_WAIT0(); }
        __syncthreads();
        uint32_t* Ah = sm + (ch & 1) * 18432;
        uint32_t* Al = Ah + 4608;
        uint32_t* Bh = Al + 4608;
        uint32_t* Bl = Bh + 4608;
#pragma unroll
        for (int ks = 0; ks < 4; ++ks) {
            int kb = ks * 8;
            uint32_t ah[4], al[4];
            ah[0] = Ah[r * ASTRIDE + kb + kq];     ah[1] = Ah[(r + 8) * ASTRIDE + kb + kq];
            ah[2] = Ah[r * ASTRIDE + kb + 4 + kq]; ah[3] = Ah[(r + 8) * ASTRIDE + kb + 4 + kq];
            al[0] = Al[r * ASTRIDE + kb + kq];     al[1] = Al[(r + 8) * ASTRIDE + kb + kq];
            al[2] = Al[r * ASTRIDE + kb + 4 + kq]; al[3] = Al[(r + 8) * ASTRIDE + kb + 4 + kq];
#pragma unroll
            for (int nt = 0; nt < 16; ++nt) {
                int nj = nt * 8 + (lane >> 2);
                uint32_t bh[2], bl[2];
                bh[0] = Bh[nj * ASTRIDE + kb + kq]; bh[1] = Bh[nj * ASTRIDE + kb + 4 + kq];
                bl[0] = Bl[nj * ASTRIDE + kb + kq]; bl[1] = Bl[nj * ASTRIDE + kb + 4 + kq];
                mma16816(c + nt * 4, ah, bh);
                mma16816(c + nt * 4, ah, bl);
                mma16816(c + nt * 4, al, bh);
            }
        }
    }

    float s1a = 0.f, s2a = 0.f, s1b = 0.f, s2b = 0.f;
#pragma unroll
    for (int nt = 0; nt < 16; ++nt) {
        int col = nt * 8 + 2 * kq;
        float y0 = c[nt * 4 + 0] + lb[col], y1 = c[nt * 4 + 1] + lb[col + 1];
        float y2 = c[nt * 4 + 2] + lb[col], y3 = c[nt * 4 + 3] + lb[col + 1];
        c[nt * 4 + 0] = y0; c[nt * 4 + 1] = y1; c[nt * 4 + 2] = y2; c[nt * 4 + 3] = y3;
        s1a += y0 + y1; s2a += y0 * y0 + y1 * y1;
        s1b += y2 + y3; s2b += y2 * y2 + y3 * y3;
    }
#pragma unroll
    for (int o = 1; o <= 2; o <<= 1) {
        s1a += __shfl_xor_sync(0xffffffffu, s1a, o);
        s2a += __shfl_xor_sync(0xffffffffu, s2a, o);
        s1b += __shfl_xor_sync(0xffffffffu, s1b, o);
        s2b += __shfl_xor_sync(0xffffffffu, s2b, o);
    }
    float mua = s1a * (1.f / 128.f), mub = s1b * (1.f / 128.f);
    float rsa = rsqrtf(s2a * (1.f / 128.f) - mua * mua + 1e-5f);
    float rsb = rsqrtf(s2b * (1.f / 128.f) - mub * mub + 1e-5f);

    int na = base + r, nbd = na + 8;
#pragma unroll
    for (int nt = 0; nt < 16; ++nt) {
        int col = nt * 8 + 2 * kq;
        int wi = nt * 4 + kq;
        float gg0 = lgg[col], gg1 = lgg[col + 1], bb0 = lbb[col], bb1 = lbb[col + 1];
        float o0 = (c[nt * 4 + 0] - mua) * rsa * gg0 + bb0;
        float o1 = (c[nt * 4 + 1] - mua) * rsa * gg1 + bb1;
        float o2 = (c[nt * 4 + 2] - mub) * rsb * gg0 + bb0;
        float o3 = (c[nt * 4 + 3] - mub) * rsb * gg1 + bb1;
        if (layer == 0) {
            if (na < n) {
                *(float2*)&g_xB[(size_t)na * HID + col] = make_float2(o0, o1);
                uint32_t hw, lw; pkpair(o0, o1, hw, lw);
                g_xhB[(size_t)na * 64 + wi] = hw; g_xlB[(size_t)na * 64 + wi] = lw;
            }
            if (nbd < n) {
                *(float2*)&g_xB[(size_t)nbd * HID + col] = make_float2(o2, o3);
                uint32_t hw, lw; pkpair(o2, o3, hw, lw);
                g_xhB[(size_t)nbd * 64 + wi] = hw; g_xlB[(size_t)nbd * 64 + wi] = lw;
            }
        } else {
            float v0 = (na < n ? o0 : 0.f) + (nbd < n ? o2 : 0.f);
            float v1 = (na < n ? o1 : 0.f) + (nbd < n ? o3 : 0.f);
#pragma unroll
            for (int off = 4; off <= 16; off <<= 1) {
                v0 += __shfl_xor_sync(0xffffffffu, v0, off);
                v1 += __shfl_xor_sync(0xffffffffu, v1, off);
            }
            if (lane < 4) { atomicAdd(&psum[col], v0); atomicAdd(&psum[col + 1], v1); }
        }
    }
    if (layer == 1) {
        __syncthreads();
        if (tid < 128) atomicAdd(&g_pooled[tid], psum[tid]);
    }
}

// ---- head ----
__global__ void k_final(const float* __restrict__ reg_w, const float* __restrict__ reg_b,
                        float* __restrict__ out, int n) {
    int tid = threadIdx.x;
    float v = g_pooled[tid] * (1.f / (float)n) * reg_w[tid];
#pragma unroll
    for (int o = 16; o; o >>= 1) v += __shfl_xor_sync(0xffffffffu, v, o);
    __shared__ float r[4];
    if ((tid & 31) == 0) r[tid >> 5] = v;
    __syncthreads();
    if (tid == 0) out[0] = r[0] + r[1] + r[2] + r[3] + reg_b[0];
}

extern "C" void kernel_launch(void* const* d_in, const int* in_sizes, int n_in,
                              void* d_out, int out_size) {
    const int*   z          = (const int*)d_in[0];
    const int*   node_type  = (const int*)d_in[1];
    const int*   edge_index = (const int*)d_in[2];
    const int*   edge_type  = (const int*)d_in[3];
    const float* z_embed    = (const float*)d_in[4];
    const float* enc_w1     = (const float*)d_in[5];
    const float* enc_b1     = (const float*)d_in[6];
    const float* enc_w2     = (const float*)d_in[7];
    const float* enc_b2     = (const float*)d_in[8];
    const float* lin_w      = (const float*)d_in[9];
    const float* lin_b      = (const float*)d_in[10];
    const float* rel_w      = (const float*)d_in[11];
    const float* ln_g       = (const float*)d_in[12];
    const float* ln_b       = (const float*)d_in[13];
    const float* reg_w      = (const float*)d_in[14];
    const float* reg_b      = (const float*)d_in[15];
    float* out = (float*)d_out;

    int n = in_sizes[0];
    int E = in_sizes[3];
    int nb = (n + 1023) / 1024;
    const int ESM = (2 * 128 * HSTRIDE + 2 * 128 * ASTRIDE) * 4;  // 106496
    const int GSM = 147456;
    cudaFuncSetAttribute(k_gemm_mma, cudaFuncAttributeMaxDynamicSharedMemorySize, GSM);
    cudaFuncSetAttribute(k_encoder_mma, cudaFuncAttributeMaxDynamicSharedMemorySize, ESM);

    k_init<<<(n + 255) / 256, 256>>>(n);
    k_setup<<<(E + 255) / 256, 256>>>(node_type, edge_index, lin_w, rel_w, enc_w1, enc_w2, n, E);
    k_scan12<<<nb, 256>>>(n, nb);
    dim3 egrid((n + 127) / 128, 4);
    k_encoder_mma<<<egrid, 256, ESM>>>(z, z_embed, enc_b1, enc_b2, n);   // 4th launch (profiled)
    k_scan3<<<nb, 256>>>(n);
    k_scatter<<<(E + 255) / 256, 256>>>(edge_index, edge_type, E);

    int agrid = (n * 32 + 255) / 256;
    int ggrid = (n + 127) / 128;
    k_aggregate<<<agrid, 256>>>(0, n);
    k_gemm_mma<<<ggrid, 256, GSM>>>(0, lin_b, ln_g, ln_b, n);
    k_aggregate<<<agrid, 256>>>(1, n);
    k_gemm_mma<<<ggrid, 256, GSM>>>(1, lin_b, ln_g, ln_b, n);

    k_final<<<1, 128>>>(reg_w, reg_b, out, n);
}